// round 13
// baseline (speedup 1.0000x reference)
#include <cuda_runtime.h>
#include <cuda_fp16.h>
#include <math.h>
#include <stdint.h>

#define B_    256
#define T_    64
#define NAG   10
#define NFEAT 4
#define XDIM  44
#define XPERM 40
#define XSTAT 10
#define HIDD  128
#define XEMBD 32
#define NHIDD 8
#define E_    90
#define M_    (B_ * T_)      // 16384
#define KD    768            // padded from 763
#define ND    640            // logical: 128 (a) + 128 (o) + 384 (gi)
#define GID   384            // stored C width (gi only)
#define OUTW  130

// ---- scratch ----
__device__ __align__(16) __half g_Uh[(size_t)M_ * KD];    // 24 MB
__device__ __align__(16) __half g_Wh[(size_t)ND * KD];    // 0.94 MB (n-major)
__device__ __align__(16) float g_bias[ND];
__device__ __align__(16) float g_C[(size_t)M_ * GID];     // 25 MB (gi only)

// ------------------------------------------------------------------ PTX helpers
__device__ __forceinline__ uint32_t smem_u32(const void* p) {
    uint32_t a;
    asm("{ .reg .u64 t; cvta.to.shared.u64 t, %1; cvt.u32.u64 %0, t; }" : "=r"(a) : "l"(p));
    return a;
}
__device__ __forceinline__ void cpasync16(uint32_t dst, const void* src) {
    asm volatile("cp.async.cg.shared.global [%0], [%1], 16;" :: "r"(dst), "l"(src) : "memory");
}
#define CP_COMMIT() asm volatile("cp.async.commit_group;" ::: "memory")
#define CP_WAIT(n)  asm volatile("cp.async.wait_group %0;" :: "n"(n) : "memory")

__device__ __forceinline__ void ldsm_x4(uint32_t& r0, uint32_t& r1, uint32_t& r2, uint32_t& r3,
                                        uint32_t addr) {
    asm volatile("ldmatrix.sync.aligned.m8n8.x4.shared.b16 {%0,%1,%2,%3}, [%4];"
                 : "=r"(r0), "=r"(r1), "=r"(r2), "=r"(r3) : "r"(addr));
}
__device__ __forceinline__ void ldsm_x2(uint32_t& r0, uint32_t& r1, uint32_t addr) {
    asm volatile("ldmatrix.sync.aligned.m8n8.x2.shared.b16 {%0,%1}, [%2];"
                 : "=r"(r0), "=r"(r1) : "r"(addr));
}
__device__ __forceinline__ void mma16816(float* d, uint32_t a0, uint32_t a1, uint32_t a2,
                                         uint32_t a3, uint32_t b0, uint32_t b1) {
    asm volatile("mma.sync.aligned.m16n8k16.row.col.f32.f16.f16.f32 "
                 "{%0,%1,%2,%3}, {%4,%5,%6,%7}, {%8,%9}, {%0,%1,%2,%3};"
                 : "+f"(d[0]), "+f"(d[1]), "+f"(d[2]), "+f"(d[3])
                 : "r"(a0), "r"(a1), "r"(a2), "r"(a3), "r"(b0), "r"(b1));
}
// fp16-accumulator MMA: D (2 packed regs) = A*B + D
__device__ __forceinline__ void mma16816h(uint32_t* d, uint32_t a0, uint32_t a1, uint32_t a2,
                                          uint32_t a3, uint32_t b0, uint32_t b1) {
    asm volatile("mma.sync.aligned.m16n8k16.row.col.f16.f16.f16.f16 "
                 "{%0,%1}, {%2,%3,%4,%5}, {%6,%7}, {%0,%1};"
                 : "+r"(d[0]), "+r"(d[1])
                 : "r"(a0), "r"(a1), "r"(a2), "r"(a3), "r"(b0), "r"(b1));
}
__device__ __forceinline__ float tanh_fast(float x) {
    float y;
    asm("tanh.approx.f32 %0, %1;" : "=f"(y) : "f"(x));
    return y;
}
__device__ __forceinline__ float sig_fast(float x) {
    return 0.5f + 0.5f * tanh_fast(0.5f * x);
}
__device__ __forceinline__ uint32_t f2h2(float lo, float hi) {
    uint32_t r;
    asm("cvt.rn.f16x2.f32 %0, %2, %1;" : "=r"(r) : "f"(lo), "f"(hi));
    return r;
}
__device__ __forceinline__ float2 h2f2(uint32_t p) {
    __half2 v = *reinterpret_cast<__half2*>(&p);
    return __half22float2(v);
}

// ------------------------------------------------------------------ feat: one WARP per (b,t); demo fused in
__device__ __forceinline__ float elu1(float v) { return v > 0.f ? v : __expf(v) - 1.f; }

#define FWARPS 8

struct FeatScratch {
    float x[XDIM];
    float h1[NAG * NHIDD];
    float p[2][NAG][NHIDD];
    float h2a[E_ * NHIDD];
};

__global__ __launch_bounds__(FWARPS * 32) void feat_kernel(
        const float* __restrict__ x,
        const float* __restrict__ ft,
        const float* __restrict__ xd,   const float* __restrict__ Wst,
        const float* __restrict__ bst,
        const float* __restrict__ Wm1a, const float* __restrict__ bm1a,
        const float* __restrict__ Wm1b, const float* __restrict__ bm1b,
        const float* __restrict__ Wm2a, const float* __restrict__ bm2a,
        const float* __restrict__ Wm2b, const float* __restrict__ bm2b,
        const float* __restrict__ Wx2,  const float* __restrict__ bx2) {
    __shared__ FeatScratch sc[FWARPS];
    int w = threadIdx.x >> 5;
    int lane = threadIdx.x & 31;
    int m = blockIdx.x * FWARPS + w;
    int b = m / T_, t = m % T_;
    FeatScratch& s = sc[w];

    const float* xr = x + ((size_t)b * (T_ + 1) + t) * XDIM;
    s.x[lane] = xr[lane];
    if (lane < XDIM - 32) s.x[32 + lane] = xr[32 + lane];
    __syncwarp();

    float h1a_reg[3];
#pragma unroll
    for (int ii = 0; ii < 3; ii++) {
        int i = lane + ii * 32;
        if (i < NAG * NHIDD) {
            int a = i / NHIDD, o = i % NHIDD;
            float acc = bm1a[o];
#pragma unroll
            for (int f = 0; f < NFEAT; f++) acc += s.x[a * NFEAT + f] * Wm1a[o * NFEAT + f];
            h1a_reg[ii] = elu1(acc);
        }
    }
#pragma unroll
    for (int ii = 0; ii < 3; ii++) {
        int i = lane + ii * 32;
        if (i < NAG * NHIDD) s.h1[i] = h1a_reg[ii];
    }
    __syncwarp();
    float h1_reg[3];
#pragma unroll
    for (int ii = 0; ii < 3; ii++) {
        int i = lane + ii * 32;
        if (i < NAG * NHIDD) {
            int a = i / NHIDD, o = i % NHIDD;
            float acc = bm1b[o];
#pragma unroll
            for (int k = 0; k < NHIDD; k++) acc += s.h1[a * NHIDD + k] * Wm1b[o * NHIDD + k];
            h1_reg[ii] = elu1(acc);
        }
    }
    __syncwarp();
#pragma unroll
    for (int ii = 0; ii < 3; ii++) {
        int i = lane + ii * 32;
        if (i < NAG * NHIDD) s.h1[i] = h1_reg[ii];
    }
    __syncwarp();

#pragma unroll
    for (int ii = 0; ii < 5; ii++) {
        int i = lane + ii * 32;
        int part = i / (NAG * NHIDD);
        int rest = i % (NAG * NHIDD);
        int a = rest / NHIDD, o = rest % NHIDD;
        float acc = 0.f;
#pragma unroll
        for (int k = 0; k < NHIDD; k++)
            acc += s.h1[a * NHIDD + k] * Wm2a[o * 16 + part * 8 + k];
        s.p[part][a][o] = acc;
    }
    __syncwarp();

    for (int i = lane; i < E_ * NHIDD; i += 32) {
        int e = i / NHIDD, o = i % NHIDD;
        int r = e / (NAG - 1), jj = e % (NAG - 1);
        int sd = jj < r ? jj : jj + 1;
        s.h2a[i] = elu1(s.p[0][r][o] + s.p[1][sd][o] + bm2a[o]);
    }
    __syncwarp();

    __half* u = g_Uh + (size_t)m * KD;
    for (int i = lane; i < E_ * NHIDD; i += 32) {
        int e = i / NHIDD, o = i % NHIDD;
        float acc = bm2b[o];
#pragma unroll
        for (int k = 0; k < NHIDD; k++) acc += s.h2a[e * NHIDD + k] * Wm2b[o * NHIDD + k];
        u[43 + i] = __float2half(elu1(acc));
    }

    {
        float acc = bx2[lane];
#pragma unroll
        for (int f = 0; f < XDIM - XPERM; f++)
            acc += s.x[XPERM + f] * Wx2[lane * (XDIM - XPERM) + f];
        u[lane] = __float2half(acc);
    }
    if (lane < XSTAT) {
        float acc = bst[lane];
        const float* xdr = xd + (size_t)b * XSTAT;
#pragma unroll
        for (int k = 0; k < XSTAT; k++) acc += xdr[k] * Wst[lane * XSTAT + k];
        u[XEMBD + lane] = __float2half(acc);
    }
    if (lane == 10) u[42] = __float2half(ft[(size_t)b * (T_ + 1) + t]);
    if (lane >= 11 && lane < 16) u[752 + lane] = __float2half(0.f);   // pad 763..767
}

// ------------------------------------------------------------------ repack W -> fp16, n-major; zero out[:,0:2]
__global__ void repack_kernel(const float* __restrict__ Wa1, const float* __restrict__ ba1,
                              const float* __restrict__ Wo1, const float* __restrict__ bo1,
                              const float* __restrict__ Wih, const float* __restrict__ bih,
                              float* __restrict__ out) {
    int idx = blockIdx.x * blockDim.x + threadIdx.x;
    if (idx < ND)
        g_bias[idx] = idx < 128 ? ba1[idx] : (idx < 256 ? bo1[idx - 128] : bih[idx - 256]);

    int stride = gridDim.x * blockDim.x;
    for (int i = idx; i < 2 * M_; i += stride)
        out[(size_t)(i >> 1) * OUTW + (i & 1)] = 0.f;

    for (int i = idx; i < KD * ND; i += stride) {
        int n = i / KD, k = i % KD;
        float v = 0.f;
        if (n < 128) {
            if (k >= 32 && k < 42)       v = Wa1[n * 730 + (k - 32)];
            else if (k >= 43 && k < 763) v = Wa1[n * 730 + 10 + (k - 43)];
        } else if (n < 256) {
            if (k < 763) v = Wo1[(n - 128) * 763 + k];
        } else {
            int r = n - 256;
            if (k < 32)                  v = Wih[r * 753 + k];
            else if (k == 42)            v = Wih[r * 753 + 32];
            else if (k >= 43 && k < 763) v = Wih[r * 753 + 33 + (k - 43)];
        }
        g_Wh[(size_t)n * KD + k] = __float2half(v);
    }
}

// ------------------------------------------------------------------ HMMA GEMM (fp16 inputs, fp32 accum), heads fused
#define BK      64
#define NCHUNK  (KD / BK)             // 12
#define TILEB   (128 * BK * 2)        // 16 KB
#define STAGEB  (2 * TILEB)           // 32 KB
#define NSTAGE  4
#define SMEMB   (NSTAGE * STAGEB)     // 128 KB

__device__ __forceinline__ void load_chunk(uint32_t stage, int m0, int n0,
                                           int koff, int tid) {
    uint32_t sA = stage, sB = stage + TILEB;
#pragma unroll
    for (int t = 0; t < 2; t++) {
        int i = tid + t * 512;
        int row = i >> 3, cc = i & 7;
        uint32_t off = row * 128 + cc * 16;
        uint32_t sw = off ^ ((off >> 3) & 0x70);
        cpasync16(sA + sw, g_Uh + (size_t)(m0 + row) * KD + koff + cc * 8);
        cpasync16(sB + sw, g_Wh + (size_t)(n0 + row) * KD + koff + cc * 8);
    }
}

__global__ __launch_bounds__(512, 1) void gemm_hmma_kernel(
        const float* __restrict__ Wa2, const float* __restrict__ Wo2,
        float* __restrict__ out) {
    extern __shared__ char smem[];
    uint32_t sb = smem_u32(smem);
    int tid = threadIdx.x;
    int wid = tid >> 5, lane = tid & 31;
    int m0 = blockIdx.y * 128;
    int n0 = blockIdx.x * 128;
    int wm = (wid & 3) * 32;
    int wn = (wid >> 2) * 32;

    int arow = (lane & 7) + ((lane >> 3) & 1) * 8;
    int akc  = (lane >> 4) * 8;
    int l2   = lane & 15;
    int brow = l2 & 7;
    int bkc  = ((l2 >> 3) & 1) * 8;

    float acc[2][4][4];
#pragma unroll
    for (int mt = 0; mt < 2; mt++)
#pragma unroll
        for (int nt = 0; nt < 4; nt++)
#pragma unroll
            for (int r = 0; r < 4; r++) acc[mt][nt][r] = 0.f;

#pragma unroll
    for (int c = 0; c < 3; c++) {
        load_chunk(sb + c * STAGEB, m0, n0, c * BK, tid);
        CP_COMMIT();
    }

    for (int c = 0; c < NCHUNK; c++) {
        if (c + 3 < NCHUNK) CP_WAIT(2); else CP_WAIT(0);
        __syncthreads();
        if (c + 3 < NCHUNK) {
            load_chunk(sb + ((c + 3) & 3) * STAGEB, m0, n0, (c + 3) * BK, tid);
            CP_COMMIT();
        }

        uint32_t sA = sb + (c & 3) * STAGEB;
        uint32_t sB = sA + TILEB;
#pragma unroll
        for (int ks = 0; ks < 4; ks++) {
            uint32_t a[2][4];
#pragma unroll
            for (int mt = 0; mt < 2; mt++) {
                uint32_t off = (uint32_t)(wm + mt * 16 + arow) * 128 + (ks * 16 + akc) * 2;
                off ^= (off >> 3) & 0x70;
                ldsm_x4(a[mt][0], a[mt][1], a[mt][2], a[mt][3], sA + off);
            }
#pragma unroll
            for (int nt = 0; nt < 4; nt++) {
                uint32_t off = (uint32_t)(wn + nt * 8 + brow) * 128 + (ks * 16 + bkc) * 2;
                off ^= (off >> 3) & 0x70;
                uint32_t b0, b1;
                ldsm_x2(b0, b1, sB + off);
#pragma unroll
                for (int mt = 0; mt < 2; mt++)
                    mma16816(acc[mt][nt], a[mt][0], a[mt][1], a[mt][2], a[mt][3], b0, b1);
            }
        }
    }

    int tq = lane >> 2, tr = lane & 3;

    if (blockIdx.x >= 2) {
        int cb = n0 - 256;
#pragma unroll
        for (int nt = 0; nt < 4; nt++) {
            int col = wn + nt * 8 + tr * 2;
            float2 bv = *(const float2*)&g_bias[n0 + col];
#pragma unroll
            for (int mt = 0; mt < 2; mt++) {
                size_t row0 = (size_t)m0 + wm + mt * 16 + tq;
                float2 v0 = {acc[mt][nt][0] + bv.x, acc[mt][nt][1] + bv.y};
                float2 v1 = {acc[mt][nt][2] + bv.x, acc[mt][nt][3] + bv.y};
                *(float2*)(g_C + row0 * GID + cb + col) = v0;
                *(float2*)(g_C + (row0 + 8) * GID + cb + col) = v1;
            }
        }
    } else {
        const float* w2 = blockIdx.x == 0 ? Wa2 : Wo2;
        int hid = blockIdx.x;
        float part[2][2] = {{0.f, 0.f}, {0.f, 0.f}};
#pragma unroll
        for (int nt = 0; nt < 4; nt++) {
            int col = wn + nt * 8 + tr * 2;
            float2 bv = *(const float2*)&g_bias[n0 + col];
            float w0 = w2[col], w1 = w2[col + 1];
#pragma unroll
            for (int mt = 0; mt < 2; mt++) {
                part[mt][0] += fmaxf(acc[mt][nt][0] + bv.x, 0.f) * w0
                             + fmaxf(acc[mt][nt][1] + bv.y, 0.f) * w1;
                part[mt][1] += fmaxf(acc[mt][nt][2] + bv.x, 0.f) * w0
                             + fmaxf(acc[mt][nt][3] + bv.y, 0.f) * w1;
            }
        }
#pragma unroll
        for (int mt = 0; mt < 2; mt++)
#pragma unroll
            for (int h = 0; h < 2; h++) {
                part[mt][h] += __shfl_xor_sync(0xFFFFFFFFu, part[mt][h], 1);
                part[mt][h] += __shfl_xor_sync(0xFFFFFFFFu, part[mt][h], 2);
            }
        if (tr == 0) {
#pragma unroll
            for (int mt = 0; mt < 2; mt++) {
                size_t row0 = (size_t)m0 + wm + mt * 16 + tq;
                atomicAdd(out + row0 * OUTW + hid, part[mt][0]);
                atomicAdd(out + (row0 + 8) * OUTW + hid, part[mt][1]);
            }
        }
    }
}

// ------------------------------------------------------------------ GRU scan via HMMA, DUAL batch-group interleave.
// 16 sequences/block (2 independent groups of 8). W_hh fragments shared
// across groups; gi via cp.async double-buffered smem; fp16 accumulators.
// One barrier per step covers both groups -> dependency latency of group A
// hidden by group B's instruction stream.
#define GBATCH 8
#define HP16   136                  // halves per h row (272 B)
#define GIP    388                  // floats per gi row (1552 B, 16B mult, conflict-free)
#define GI_BYTES (2 * 2 * GBATCH * GIP * 4)        // 49664
#define GH_BYTES (2 * 2 * GBATCH * HP16 * 2)       // 8704
#define GRU_SMEM (GI_BYTES + GH_BYTES)             // 58368

__global__ __launch_bounds__(256, 1) void gru_mma_kernel(
        const float* __restrict__ Whh, const float* __restrict__ bhh,
        const float* __restrict__ h0,  float* __restrict__ out) {
    extern __shared__ char gsm[];
    float*  s_gi = (float*)gsm;                       // [(u*2+ph)*8 + b][GIP]
    __half* s_h  = (__half*)(gsm + GI_BYTES);         // [(u*2+ph)*8 + b][HP16]
    uint32_t sgi_u32 = smem_u32(s_gi);
    uint32_t sh_u32  = smem_u32(s_h);

    int tid = threadIdx.x;
    int wid = tid >> 5, lane = tid & 31;
    int tq = lane >> 2, tr = lane & 3;
    int l2 = lane & 15;
    int brow = l2 & 7;
    int bkc  = ((l2 >> 3) & 1) * 8;
    int bB = blockIdx.x * 16;          // 16 sequences per block
    int j0 = wid * 16 + tq;

    // static A fragments: gate g, rows g*128+j0 / +8 (shared by both groups)
    uint32_t afr[3][8][4];
#pragma unroll
    for (int g = 0; g < 3; g++)
#pragma unroll
        for (int kt = 0; kt < 8; kt++) {
            int row0 = g * HIDD + j0;
            int k0 = kt * 16 + tr * 2;
            const float* w0 = Whh + (size_t)row0 * HIDD + k0;
            const float* w1 = Whh + (size_t)(row0 + 8) * HIDD + k0;
            afr[g][kt][0] = f2h2(w0[0], w0[1]);
            afr[g][kt][1] = f2h2(w1[0], w1[1]);
            afr[g][kt][2] = f2h2(w0[8], w0[9]);
            afr[g][kt][3] = f2h2(w1[8], w1[9]);
        }
    float bb[3][2];
#pragma unroll
    for (int g = 0; g < 3; g++) {
        bb[g][0] = bhh[g * HIDD + j0];
        bb[g][1] = bhh[g * HIDD + j0 + 8];
    }

    float hreg[2][2][2];               // [group][js][bs]
    float* outb[2][2];
#pragma unroll
    for (int u = 0; u < 2; u++)
#pragma unroll
        for (int bs = 0; bs < 2; bs++) {
            int b = bB + u * 8 + 2 * tr + bs;
            hreg[u][0][bs] = h0[(size_t)b * HIDD + j0];
            hreg[u][1][bs] = h0[(size_t)b * HIDD + j0 + 8];
            outb[u][bs] = out + ((size_t)b * T_) * OUTW + 2 + j0;
        }

    // init s_h phase 0 (both groups)
    for (int i = tid; i < 2 * GBATCH * HIDD; i += 256) {
        int u = i >> 10, rest = i & 1023, b = rest >> 7, j = rest & 127;
        s_h[(size_t)((u * 2 + 0) * GBATCH + b) * HP16 + j] =
            __float2half(h0[(size_t)(bB + u * 8 + b) * HIDD + j]);
    }
    // init gi t=0 via cp.async (1536 16B-chunks, 6/thread)
#pragma unroll
    for (int i = 0; i < 6; i++) {
        int v = tid + i * 256;
        int u = v / 768, w = v % 768, b = w / 96, c16 = w % 96;
        const float* src = g_C + ((size_t)(bB + u * 8 + b) * T_) * GID + c16 * 4;
        uint32_t dst = sgi_u32 + (((u * 2 + 0) * GBATCH + b) * GIP + c16 * 4) * 4;
        cpasync16(dst, src);
    }
    CP_COMMIT();
    CP_WAIT(0);
    __syncthreads();

    for (int t = 0; t < T_; t++) {
        int p = t & 1;

        // issue cp.async prefetch of gi(t+1) into phase p^1 (both groups)
        if (t + 1 < T_) {
#pragma unroll
            for (int i = 0; i < 6; i++) {
                int v = tid + i * 256;
                int u = v / 768, w = v % 768, b = w / 96, c16 = w % 96;
                const float* src =
                    g_C + ((size_t)(bB + u * 8 + b) * T_ + t + 1) * GID + c16 * 4;
                uint32_t dst =
                    sgi_u32 + (((u * 2 + (p ^ 1)) * GBATCH + b) * GIP + c16 * 4) * 4;
                cpasync16(dst, src);
            }
            CP_COMMIT();
        }

        // MMA phase, both groups interleaved (independent chains)
        uint32_t d16[2][3][2];
#pragma unroll
        for (int u = 0; u < 2; u++)
#pragma unroll
            for (int g = 0; g < 3; g++) { d16[u][g][0] = 0u; d16[u][g][1] = 0u; }

        uint32_t hb0 = sh_u32 + (uint32_t)((0 * 2 + p) * GBATCH) * (HP16 * 2)
                     + (uint32_t)brow * (HP16 * 2) + (uint32_t)bkc * 2;
        uint32_t hb1 = sh_u32 + (uint32_t)((1 * 2 + p) * GBATCH) * (HP16 * 2)
                     + (uint32_t)brow * (HP16 * 2) + (uint32_t)bkc * 2;
#pragma unroll
        for (int kt = 0; kt < 8; kt++) {
            uint32_t a0, a1, b0, b1;
            ldsm_x2(a0, a1, hb0 + (uint32_t)kt * 32);
            ldsm_x2(b0, b1, hb1 + (uint32_t)kt * 32);
#pragma unroll
            for (int g = 0; g < 3; g++) {
                mma16816h(d16[0][g], afr[g][kt][0], afr[g][kt][1],
                          afr[g][kt][2], afr[g][kt][3], a0, a1);
                mma16816h(d16[1][g], afr[g][kt][0], afr[g][kt][1],
                          afr[g][kt][2], afr[g][kt][3], b0, b1);
            }
        }

        // gate phase, both groups; gi read from smem (latency hidden)
#pragma unroll
        for (int u = 0; u < 2; u++) {
            const float* gir0 = s_gi + (size_t)((u * 2 + p) * GBATCH + 2 * tr) * GIP + j0;
            const float* gir1 = gir0 + GIP;
#pragma unroll
            for (int js = 0; js < 2; js++) {
                float2 fd[3];
#pragma unroll
                for (int g = 0; g < 3; g++) fd[g] = h2f2(d16[u][g][js]);
                const float* g0 = gir0 + js * 8;
                const float* g1 = gir1 + js * 8;

                float r0 = sig_fast(g0[0]        + fd[0].x + bb[0][js]);
                float z0 = sig_fast(g0[HIDD]     + fd[1].x + bb[1][js]);
                float n0 = tanh_fast(g0[2 * HIDD] + r0 * (fd[2].x + bb[2][js]));
                float hv0 = (1.f - z0) * n0 + z0 * hreg[u][js][0];
                hreg[u][js][0] = hv0;

                float r1 = sig_fast(g1[0]        + fd[0].y + bb[0][js]);
                float z1 = sig_fast(g1[HIDD]     + fd[1].y + bb[1][js]);
                float n1 = tanh_fast(g1[2 * HIDD] + r1 * (fd[2].y + bb[2][js]));
                float hv1 = (1.f - z1) * n1 + z1 * hreg[u][js][1];
                hreg[u][js][1] = hv1;

                s_h[(size_t)((u * 2 + (p ^ 1)) * GBATCH + 2 * tr) * HP16 + j0 + js * 8] =
                    __float2half(hv0);
                s_h[(size_t)((u * 2 + (p ^ 1)) * GBATCH + 2 * tr + 1) * HP16 + j0 + js * 8] =
                    __float2half(hv1);
                outb[u][0][(size_t)t * OUTW + js * 8] = hv0;
                outb[u][1][(size_t)t * OUTW + js * 8] = hv1;
            }
        }

        CP_WAIT(0);
        __syncthreads();
    }
}

// ------------------------------------------------------------------
extern "C" void kernel_launch(void* const* d_in, const int* in_sizes, int n_in,
                              void* d_out, int out_size) {
    const float* x     = (const float*)d_in[0];
    const float* xdemo = (const float*)d_in[1];
    const float* ft    = (const float*)d_in[2];
    const float* h0    = (const float*)d_in[3];
    const float* Wx2   = (const float*)d_in[4];
    const float* bx2   = (const float*)d_in[5];
    const float* Wst   = (const float*)d_in[6];
    const float* bst   = (const float*)d_in[7];
    const float* Wm1a  = (const float*)d_in[8];
    const float* bm1a  = (const float*)d_in[9];
    const float* Wm1b  = (const float*)d_in[10];
    const float* bm1b  = (const float*)d_in[11];
    const float* Wm2a  = (const float*)d_in[12];
    const float* bm2a  = (const float*)d_in[13];
    const float* Wm2b  = (const float*)d_in[14];
    const float* bm2b  = (const float*)d_in[15];
    const float* Wa1   = (const float*)d_in[16];
    const float* ba1   = (const float*)d_in[17];
    const float* Wa2   = (const float*)d_in[18];
    const float* Wo1   = (const float*)d_in[19];
    const float* bo1   = (const float*)d_in[20];
    const float* Wo2   = (const float*)d_in[21];
    const float* Wih   = (const float*)d_in[22];
    const float* bih   = (const float*)d_in[23];
    const float* Whh   = (const float*)d_in[24];
    const float* bhh   = (const float*)d_in[25];
    float* out = (float*)d_out;

    cudaFuncSetAttribute(gemm_hmma_kernel,
                         cudaFuncAttributeMaxDynamicSharedMemorySize, SMEMB);
    cudaFuncSetAttribute(gru_mma_kernel,
                         cudaFuncAttributeMaxDynamicSharedMemorySize, GRU_SMEM);

    repack_kernel<<<480, 256>>>(Wa1, ba1, Wo1, bo1, Wih, bih, out);
    feat_kernel<<<M_ / FWARPS, FWARPS * 32>>>(x, ft, xdemo, Wst, bst,
                                              Wm1a, bm1a, Wm1b, bm1b,
                                              Wm2a, bm2a, Wm2b, bm2b, Wx2, bx2);
    gemm_hmma_kernel<<<dim3(ND / 128, M_ / 128), 512, SMEMB>>>(Wa2, Wo2, out);
    gru_mma_kernel<<<B_ / 16, 256, GRU_SMEM>>>(Whh, bhh, h0, out);
}

// round 14
// speedup vs baseline: 1.1864x; 1.1864x over previous
#include <cuda_runtime.h>
#include <cuda_fp16.h>
#include <math.h>
#include <stdint.h>

#define B_    256
#define T_    64
#define NAG   10
#define NFEAT 4
#define XDIM  44
#define XPERM 40
#define XSTAT 10
#define HIDD  128
#define XEMBD 32
#define NHIDD 8
#define E_    90
#define M_    (B_ * T_)      // 16384
#define KD    768            // padded from 763
#define ND    640            // logical: 128 (a) + 128 (o) + 384 (gi)
#define GID   384            // stored C width (gi only)
#define OUTW  130

// ---- scratch ----
__device__ __align__(16) __half g_Uh[(size_t)M_ * KD];    // 24 MB
__device__ __align__(16) __half g_Wh[(size_t)ND * KD];    // 0.94 MB (n-major)
__device__ __align__(16) float g_bias[ND];
__device__ __align__(16) float g_C[(size_t)M_ * GID];     // 25 MB (gi only)

// ------------------------------------------------------------------ PTX helpers
__device__ __forceinline__ uint32_t smem_u32(const void* p) {
    uint32_t a;
    asm("{ .reg .u64 t; cvta.to.shared.u64 t, %1; cvt.u32.u64 %0, t; }" : "=r"(a) : "l"(p));
    return a;
}
__device__ __forceinline__ void cpasync16(uint32_t dst, const void* src) {
    asm volatile("cp.async.cg.shared.global [%0], [%1], 16;" :: "r"(dst), "l"(src) : "memory");
}
#define CP_COMMIT() asm volatile("cp.async.commit_group;" ::: "memory")
#define CP_WAIT(n)  asm volatile("cp.async.wait_group %0;" :: "n"(n) : "memory")

__device__ __forceinline__ void ldsm_x4(uint32_t& r0, uint32_t& r1, uint32_t& r2, uint32_t& r3,
                                        uint32_t addr) {
    asm volatile("ldmatrix.sync.aligned.m8n8.x4.shared.b16 {%0,%1,%2,%3}, [%4];"
                 : "=r"(r0), "=r"(r1), "=r"(r2), "=r"(r3) : "r"(addr));
}
__device__ __forceinline__ void ldsm_x2(uint32_t& r0, uint32_t& r1, uint32_t addr) {
    asm volatile("ldmatrix.sync.aligned.m8n8.x2.shared.b16 {%0,%1}, [%2];"
                 : "=r"(r0), "=r"(r1) : "r"(addr));
}
__device__ __forceinline__ void mma16816(float* d, uint32_t a0, uint32_t a1, uint32_t a2,
                                         uint32_t a3, uint32_t b0, uint32_t b1) {
    asm volatile("mma.sync.aligned.m16n8k16.row.col.f32.f16.f16.f32 "
                 "{%0,%1,%2,%3}, {%4,%5,%6,%7}, {%8,%9}, {%0,%1,%2,%3};"
                 : "+f"(d[0]), "+f"(d[1]), "+f"(d[2]), "+f"(d[3])
                 : "r"(a0), "r"(a1), "r"(a2), "r"(a3), "r"(b0), "r"(b1));
}
__device__ __forceinline__ float tanh_fast(float x) {
    float y;
    asm("tanh.approx.f32 %0, %1;" : "=f"(y) : "f"(x));
    return y;
}
__device__ __forceinline__ float sig_fast(float x) {
    return 0.5f + 0.5f * tanh_fast(0.5f * x);
}
__device__ __forceinline__ uint32_t f2h2(float lo, float hi) {
    uint32_t r;
    asm("cvt.rn.f16x2.f32 %0, %2, %1;" : "=r"(r) : "f"(lo), "f"(hi));
    return r;
}

// ------------------------------------------------------------------ feat: one WARP per (b,t); demo fused in
__device__ __forceinline__ float elu1(float v) { return v > 0.f ? v : __expf(v) - 1.f; }

#define FWARPS 8

struct FeatScratch {
    float x[XDIM];
    float h1[NAG * NHIDD];
    float p[2][NAG][NHIDD];
    float h2a[E_ * NHIDD];
};

__global__ __launch_bounds__(FWARPS * 32) void feat_kernel(
        const float* __restrict__ x,
        const float* __restrict__ ft,
        const float* __restrict__ xd,   const float* __restrict__ Wst,
        const float* __restrict__ bst,
        const float* __restrict__ Wm1a, const float* __restrict__ bm1a,
        const float* __restrict__ Wm1b, const float* __restrict__ bm1b,
        const float* __restrict__ Wm2a, const float* __restrict__ bm2a,
        const float* __restrict__ Wm2b, const float* __restrict__ bm2b,
        const float* __restrict__ Wx2,  const float* __restrict__ bx2) {
    __shared__ FeatScratch sc[FWARPS];
    int w = threadIdx.x >> 5;
    int lane = threadIdx.x & 31;
    int m = blockIdx.x * FWARPS + w;
    int b = m / T_, t = m % T_;
    FeatScratch& s = sc[w];

    const float* xr = x + ((size_t)b * (T_ + 1) + t) * XDIM;
    s.x[lane] = xr[lane];
    if (lane < XDIM - 32) s.x[32 + lane] = xr[32 + lane];
    __syncwarp();

    float h1a_reg[3];
#pragma unroll
    for (int ii = 0; ii < 3; ii++) {
        int i = lane + ii * 32;
        if (i < NAG * NHIDD) {
            int a = i / NHIDD, o = i % NHIDD;
            float acc = bm1a[o];
#pragma unroll
            for (int f = 0; f < NFEAT; f++) acc += s.x[a * NFEAT + f] * Wm1a[o * NFEAT + f];
            h1a_reg[ii] = elu1(acc);
        }
    }
#pragma unroll
    for (int ii = 0; ii < 3; ii++) {
        int i = lane + ii * 32;
        if (i < NAG * NHIDD) s.h1[i] = h1a_reg[ii];
    }
    __syncwarp();
    float h1_reg[3];
#pragma unroll
    for (int ii = 0; ii < 3; ii++) {
        int i = lane + ii * 32;
        if (i < NAG * NHIDD) {
            int a = i / NHIDD, o = i % NHIDD;
            float acc = bm1b[o];
#pragma unroll
            for (int k = 0; k < NHIDD; k++) acc += s.h1[a * NHIDD + k] * Wm1b[o * NHIDD + k];
            h1_reg[ii] = elu1(acc);
        }
    }
    __syncwarp();
#pragma unroll
    for (int ii = 0; ii < 3; ii++) {
        int i = lane + ii * 32;
        if (i < NAG * NHIDD) s.h1[i] = h1_reg[ii];
    }
    __syncwarp();

#pragma unroll
    for (int ii = 0; ii < 5; ii++) {
        int i = lane + ii * 32;
        int part = i / (NAG * NHIDD);
        int rest = i % (NAG * NHIDD);
        int a = rest / NHIDD, o = rest % NHIDD;
        float acc = 0.f;
#pragma unroll
        for (int k = 0; k < NHIDD; k++)
            acc += s.h1[a * NHIDD + k] * Wm2a[o * 16 + part * 8 + k];
        s.p[part][a][o] = acc;
    }
    __syncwarp();

    for (int i = lane; i < E_ * NHIDD; i += 32) {
        int e = i / NHIDD, o = i % NHIDD;
        int r = e / (NAG - 1), jj = e % (NAG - 1);
        int sd = jj < r ? jj : jj + 1;
        s.h2a[i] = elu1(s.p[0][r][o] + s.p[1][sd][o] + bm2a[o]);
    }
    __syncwarp();

    __half* u = g_Uh + (size_t)m * KD;
    for (int i = lane; i < E_ * NHIDD; i += 32) {
        int e = i / NHIDD, o = i % NHIDD;
        float acc = bm2b[o];
#pragma unroll
        for (int k = 0; k < NHIDD; k++) acc += s.h2a[e * NHIDD + k] * Wm2b[o * NHIDD + k];
        u[43 + i] = __float2half(elu1(acc));
    }

    {
        float acc = bx2[lane];
#pragma unroll
        for (int f = 0; f < XDIM - XPERM; f++)
            acc += s.x[XPERM + f] * Wx2[lane * (XDIM - XPERM) + f];
        u[lane] = __float2half(acc);
    }
    if (lane < XSTAT) {
        float acc = bst[lane];
        const float* xdr = xd + (size_t)b * XSTAT;
#pragma unroll
        for (int k = 0; k < XSTAT; k++) acc += xdr[k] * Wst[lane * XSTAT + k];
        u[XEMBD + lane] = __float2half(acc);
    }
    if (lane == 10) u[42] = __float2half(ft[(size_t)b * (T_ + 1) + t]);
    if (lane >= 11 && lane < 16) u[752 + lane] = __float2half(0.f);   // pad 763..767
}

// ------------------------------------------------------------------ repack W -> fp16, n-major; zero out[:,0:2]
__global__ void repack_kernel(const float* __restrict__ Wa1, const float* __restrict__ ba1,
                              const float* __restrict__ Wo1, const float* __restrict__ bo1,
                              const float* __restrict__ Wih, const float* __restrict__ bih,
                              float* __restrict__ out) {
    int idx = blockIdx.x * blockDim.x + threadIdx.x;
    if (idx < ND)
        g_bias[idx] = idx < 128 ? ba1[idx] : (idx < 256 ? bo1[idx - 128] : bih[idx - 256]);

    int stride = gridDim.x * blockDim.x;
    for (int i = idx; i < 2 * M_; i += stride)
        out[(size_t)(i >> 1) * OUTW + (i & 1)] = 0.f;

    for (int i = idx; i < KD * ND; i += stride) {
        int n = i / KD, k = i % KD;
        float v = 0.f;
        if (n < 128) {
            if (k >= 32 && k < 42)       v = Wa1[n * 730 + (k - 32)];
            else if (k >= 43 && k < 763) v = Wa1[n * 730 + 10 + (k - 43)];
        } else if (n < 256) {
            if (k < 763) v = Wo1[(n - 128) * 763 + k];
        } else {
            int r = n - 256;
            if (k < 32)                  v = Wih[r * 753 + k];
            else if (k == 42)            v = Wih[r * 753 + 32];
            else if (k >= 43 && k < 763) v = Wih[r * 753 + 33 + (k - 43)];
        }
        g_Wh[(size_t)n * KD + k] = __float2half(v);
    }
}

// ------------------------------------------------------------------ HMMA GEMM: CTA 256x128, 8 warps of 64x64,
// BK=64, 3-stage cp.async. 128 B smem read per MMA (half of 32x32 tiles).
#define BK      64
#define NCHUNK  (KD / BK)               // 12
#define ATILEB  (256 * BK * 2)          // 32 KB
#define BTILEB  (128 * BK * 2)          // 16 KB
#define STAGEB  (ATILEB + BTILEB)       // 48 KB
#define NSTAGE  3
#define SMEMB   (NSTAGE * STAGEB)       // 144 KB

__device__ __forceinline__ void load_chunk(uint32_t stage, int m0, int n0,
                                           int koff, int tid) {
    uint32_t sA = stage, sB = stage + ATILEB;
#pragma unroll
    for (int t = 0; t < 8; t++) {          // A: 2048 16B chunks
        int i = tid + t * 256;
        int row = i >> 3, cc = i & 7;
        uint32_t off = row * 128 + cc * 16;
        uint32_t sw = off ^ ((off >> 3) & 0x70);
        cpasync16(sA + sw, g_Uh + (size_t)(m0 + row) * KD + koff + cc * 8);
    }
#pragma unroll
    for (int t = 0; t < 4; t++) {          // B: 1024 16B chunks
        int i = tid + t * 256;
        int row = i >> 3, cc = i & 7;
        uint32_t off = row * 128 + cc * 16;
        uint32_t sw = off ^ ((off >> 3) & 0x70);
        cpasync16(sB + sw, g_Wh + (size_t)(n0 + row) * KD + koff + cc * 8);
    }
}

__global__ __launch_bounds__(256) void gemm_hmma_kernel(
        const float* __restrict__ Wa2, const float* __restrict__ Wo2,
        float* __restrict__ out) {
    extern __shared__ char smem[];
    uint32_t sb = smem_u32(smem);
    int tid = threadIdx.x;
    int wid = tid >> 5, lane = tid & 31;
    int m0 = blockIdx.y * 256;
    int n0 = blockIdx.x * 128;
    int wm = (wid & 3) * 64;     // warp M offset (4 tiles of 64)
    int wn = (wid >> 2) * 64;    // warp N offset (2 tiles of 64)

    int arow = (lane & 7) + ((lane >> 3) & 1) * 8;
    int akc  = (lane >> 4) * 8;
    int l2   = lane & 15;
    int brow = l2 & 7;
    int bkc  = ((l2 >> 3) & 1) * 8;

    float acc[4][8][4];
#pragma unroll
    for (int mt = 0; mt < 4; mt++)
#pragma unroll
        for (int nt = 0; nt < 8; nt++)
#pragma unroll
            for (int r = 0; r < 4; r++) acc[mt][nt][r] = 0.f;

    // prologue: stages 0,1 <- chunks 0,1
    load_chunk(sb + 0 * STAGEB, m0, n0, 0 * BK, tid);
    CP_COMMIT();
    load_chunk(sb + 1 * STAGEB, m0, n0, 1 * BK, tid);
    CP_COMMIT();

    for (int c = 0; c < NCHUNK; c++) {
        if (c + 1 < NCHUNK) CP_WAIT(1); else CP_WAIT(0);
        __syncthreads();
        if (c + 2 < NCHUNK) {
            load_chunk(sb + ((c + 2) % 3) * STAGEB, m0, n0, (c + 2) * BK, tid);
            CP_COMMIT();
        }

        uint32_t sA = sb + (c % 3) * STAGEB;
        uint32_t sB = sA + ATILEB;
#pragma unroll
        for (int ks = 0; ks < 4; ks++) {
            uint32_t a[4][4];
#pragma unroll
            for (int mt = 0; mt < 4; mt++) {
                uint32_t off = (uint32_t)(wm + mt * 16 + arow) * 128 + (ks * 16 + akc) * 2;
                off ^= (off >> 3) & 0x70;
                ldsm_x4(a[mt][0], a[mt][1], a[mt][2], a[mt][3], sA + off);
            }
#pragma unroll
            for (int nt = 0; nt < 8; nt++) {
                uint32_t off = (uint32_t)(wn + nt * 8 + brow) * 128 + (ks * 16 + bkc) * 2;
                off ^= (off >> 3) & 0x70;
                uint32_t b0, b1;
                ldsm_x2(b0, b1, sB + off);
#pragma unroll
                for (int mt = 0; mt < 4; mt++)
                    mma16816(acc[mt][nt], a[mt][0], a[mt][1], a[mt][2], a[mt][3], b0, b1);
            }
        }
    }

    int tq = lane >> 2, tr = lane & 3;

    if (blockIdx.x >= 2) {
        int cb = n0 - 256;
#pragma unroll
        for (int nt = 0; nt < 8; nt++) {
            int col = wn + nt * 8 + tr * 2;
            float2 bv = *(const float2*)&g_bias[n0 + col];
#pragma unroll
            for (int mt = 0; mt < 4; mt++) {
                size_t row0 = (size_t)m0 + wm + mt * 16 + tq;
                float2 v0 = {acc[mt][nt][0] + bv.x, acc[mt][nt][1] + bv.y};
                float2 v1 = {acc[mt][nt][2] + bv.x, acc[mt][nt][3] + bv.y};
                *(float2*)(g_C + row0 * GID + cb + col) = v0;
                *(float2*)(g_C + (row0 + 8) * GID + cb + col) = v1;
            }
        }
    } else {
        const float* w2 = blockIdx.x == 0 ? Wa2 : Wo2;
        int hid = blockIdx.x;
        float part[4][2];
#pragma unroll
        for (int mt = 0; mt < 4; mt++) { part[mt][0] = 0.f; part[mt][1] = 0.f; }
#pragma unroll
        for (int nt = 0; nt < 8; nt++) {
            int col = wn + nt * 8 + tr * 2;
            float2 bv = *(const float2*)&g_bias[n0 + col];
            float w0 = w2[col], w1 = w2[col + 1];
#pragma unroll
            for (int mt = 0; mt < 4; mt++) {
                part[mt][0] += fmaxf(acc[mt][nt][0] + bv.x, 0.f) * w0
                             + fmaxf(acc[mt][nt][1] + bv.y, 0.f) * w1;
                part[mt][1] += fmaxf(acc[mt][nt][2] + bv.x, 0.f) * w0
                             + fmaxf(acc[mt][nt][3] + bv.y, 0.f) * w1;
            }
        }
#pragma unroll
        for (int mt = 0; mt < 4; mt++)
#pragma unroll
            for (int h = 0; h < 2; h++) {
                part[mt][h] += __shfl_xor_sync(0xFFFFFFFFu, part[mt][h], 1);
                part[mt][h] += __shfl_xor_sync(0xFFFFFFFFu, part[mt][h], 2);
            }
        if (tr == 0) {
#pragma unroll
            for (int mt = 0; mt < 4; mt++) {
                size_t row0 = (size_t)m0 + wm + mt * 16 + tq;
                atomicAdd(out + row0 * OUTW + hid, part[mt][0]);
                atomicAdd(out + (row0 + 8) * OUTW + hid, part[mt][1]);
            }
        }
    }
}

// ------------------------------------------------------------------ GRU scan via HMMA (R11 structure, best at 69 us).
#define GBATCH 8
#define HP16   136

__global__ __launch_bounds__(256, 1) void gru_mma_kernel(
        const float* __restrict__ Whh, const float* __restrict__ bhh,
        const float* __restrict__ h0,  float* __restrict__ out) {
    __shared__ __align__(16) __half s_h16[2][GBATCH][HP16];

    int tid = threadIdx.x;
    int wid = tid >> 5, lane = tid & 31;
    int tq = lane >> 2, tr = lane & 3;
    int l2 = lane & 15;
    int brow = l2 & 7;
    int bkc  = ((l2 >> 3) & 1) * 8;
    int b0g = blockIdx.x * GBATCH;
    int j0 = wid * 16 + tq;

    uint32_t sh_base = smem_u32(&s_h16[0][0][0]);

    uint32_t afr[3][8][4];
#pragma unroll
    for (int g = 0; g < 3; g++)
#pragma unroll
        for (int kt = 0; kt < 8; kt++) {
            int row0 = g * HIDD + j0;
            int k0 = kt * 16 + tr * 2;
            const float* w0 = Whh + (size_t)row0 * HIDD + k0;
            const float* w1 = Whh + (size_t)(row0 + 8) * HIDD + k0;
            afr[g][kt][0] = f2h2(w0[0], w0[1]);
            afr[g][kt][1] = f2h2(w1[0], w1[1]);
            afr[g][kt][2] = f2h2(w0[8], w0[9]);
            afr[g][kt][3] = f2h2(w1[8], w1[9]);
        }
    float bb[3][2];
#pragma unroll
    for (int g = 0; g < 3; g++) {
        bb[g][0] = bhh[g * HIDD + j0];
        bb[g][1] = bhh[g * HIDD + j0 + 8];
    }

    float hreg[2][2];
    const float* gibase[2];
    float* outbase[2];
#pragma unroll
    for (int bs = 0; bs < 2; bs++) {
        int b = b0g + 2 * tr + bs;
        hreg[0][bs] = h0[(size_t)b * HIDD + j0];
        hreg[1][bs] = h0[(size_t)b * HIDD + j0 + 8];
        gibase[bs] = g_C + ((size_t)b * T_) * GID + j0;
        outbase[bs] = out + ((size_t)b * T_) * OUTW + 2 + j0;
    }
    for (int i = tid; i < GBATCH * HIDD; i += 256)
        s_h16[0][i >> 7][i & 127] =
            __float2half(h0[(size_t)(b0g + (i >> 7)) * HIDD + (i & 127)]);

    float gic[3][4], gin[3][4];
#pragma unroll
    for (int g = 0; g < 3; g++)
#pragma unroll
        for (int js = 0; js < 2; js++)
#pragma unroll
            for (int bs = 0; bs < 2; bs++)
                gic[g][js * 2 + bs] = gibase[bs][g * HIDD + js * 8];
    __syncthreads();

    for (int t = 0; t < T_; t++) {
        if (t + 1 < T_) {
#pragma unroll
            for (int g = 0; g < 3; g++)
#pragma unroll
                for (int js = 0; js < 2; js++)
#pragma unroll
                    for (int bs = 0; bs < 2; bs++)
                        gin[g][js * 2 + bs] =
                            gibase[bs][(size_t)(t + 1) * GID + g * HIDD + js * 8];
        }

        int p = t & 1;
        uint32_t hb = sh_base + (uint32_t)p * (GBATCH * HP16 * 2)
                    + (uint32_t)brow * (HP16 * 2) + (uint32_t)bkc * 2;

        float d[3][4], e[3][4];
#pragma unroll
        for (int js = 0; js < 2; js++)
#pragma unroll
            for (int bs = 0; bs < 2; bs++) {
                int q = js * 2 + bs;
                d[0][q] = gic[0][q] + bb[0][js];
                d[1][q] = gic[1][q] + bb[1][js];
                d[2][q] = bb[2][js];
                e[0][q] = 0.f; e[1][q] = 0.f; e[2][q] = 0.f;
            }

#pragma unroll
        for (int kt = 0; kt < 8; kt++) {
            uint32_t bf0, bf1;
            ldsm_x2(bf0, bf1, hb + (uint32_t)kt * 32);
            float* dst0 = (kt < 4) ? d[0] : e[0];
            float* dst1 = (kt < 4) ? d[1] : e[1];
            float* dst2 = (kt < 4) ? d[2] : e[2];
            mma16816(dst0, afr[0][kt][0], afr[0][kt][1], afr[0][kt][2], afr[0][kt][3], bf0, bf1);
            mma16816(dst1, afr[1][kt][0], afr[1][kt][1], afr[1][kt][2], afr[1][kt][3], bf0, bf1);
            mma16816(dst2, afr[2][kt][0], afr[2][kt][1], afr[2][kt][2], afr[2][kt][3], bf0, bf1);
        }

#pragma unroll
        for (int js = 0; js < 2; js++)
#pragma unroll
            for (int bs = 0; bs < 2; bs++) {
                int q = js * 2 + bs;
                float r = sig_fast(d[0][q] + e[0][q]);
                float z = sig_fast(d[1][q] + e[1][q]);
                float n = tanh_fast(gic[2][q] + r * (d[2][q] + e[2][q]));
                float hv = (1.f - z) * n + z * hreg[js][bs];
                hreg[js][bs] = hv;
                s_h16[p ^ 1][2 * tr + bs][j0 + js * 8] = __float2half(hv);
                outbase[bs][(size_t)t * OUTW + js * 8] = hv;
            }

#pragma unroll
        for (int g = 0; g < 3; g++)
#pragma unroll
            for (int q = 0; q < 4; q++) gic[g][q] = gin[g][q];
        __syncthreads();
    }
}

// ------------------------------------------------------------------
extern "C" void kernel_launch(void* const* d_in, const int* in_sizes, int n_in,
                              void* d_out, int out_size) {
    const float* x     = (const float*)d_in[0];
    const float* xdemo = (const float*)d_in[1];
    const float* ft    = (const float*)d_in[2];
    const float* h0    = (const float*)d_in[3];
    const float* Wx2   = (const float*)d_in[4];
    const float* bx2   = (const float*)d_in[5];
    const float* Wst   = (const float*)d_in[6];
    const float* bst   = (const float*)d_in[7];
    const float* Wm1a  = (const float*)d_in[8];
    const float* bm1a  = (const float*)d_in[9];
    const float* Wm1b  = (const float*)d_in[10];
    const float* bm1b  = (const float*)d_in[11];
    const float* Wm2a  = (const float*)d_in[12];
    const float* bm2a  = (const float*)d_in[13];
    const float* Wm2b  = (const float*)d_in[14];
    const float* bm2b  = (const float*)d_in[15];
    const float* Wa1   = (const float*)d_in[16];
    const float* ba1   = (const float*)d_in[17];
    const float* Wa2   = (const float*)d_in[18];
    const float* Wo1   = (const float*)d_in[19];
    const float* bo1   = (const float*)d_in[20];
    const float* Wo2   = (const float*)d_in[21];
    const float* Wih   = (const float*)d_in[22];
    const float* bih   = (const float*)d_in[23];
    const float* Whh   = (const float*)d_in[24];
    const float* bhh   = (const float*)d_in[25];
    float* out = (float*)d_out;

    cudaFuncSetAttribute(gemm_hmma_kernel,
                         cudaFuncAttributeMaxDynamicSharedMemorySize, SMEMB);

    repack_kernel<<<480, 256>>>(Wa1, ba1, Wo1, bo1, Wih, bih, out);
    feat_kernel<<<M_ / FWARPS, FWARPS * 32>>>(x, ft, xdemo, Wst, bst,
                                              Wm1a, bm1a, Wm1b, bm1b,
                                              Wm2a, bm2a, Wm2b, bm2b, Wx2, bx2);
    gemm_hmma_kernel<<<dim3(ND / 128, M_ / 256), 256, SMEMB>>>(Wa2, Wo2, out);
    gru_mma_kernel<<<B_ / GBATCH, 256>>>(Whh, bhh, h0, out);
}

// round 15
// speedup vs baseline: 1.3269x; 1.1184x over previous
#include <cuda_runtime.h>
#include <cuda_fp16.h>
#include <math.h>
#include <stdint.h>

#define B_    256
#define T_    64
#define NAG   10
#define NFEAT 4
#define XDIM  44
#define XPERM 40
#define XSTAT 10
#define HIDD  128
#define XEMBD 32
#define NHIDD 8
#define E_    90
#define M_    (B_ * T_)      // 16384
#define KD    768            // padded from 763
#define ND    640            // logical: 128 (a) + 128 (o) + 384 (gi)
#define GID   384            // stored C width (gi only)
#define OUTW  130

// ---- scratch ----
__device__ __align__(16) __half g_Uh[(size_t)M_ * KD];    // 24 MB
__device__ __align__(16) __half g_Wh[(size_t)ND * KD];    // 0.94 MB (n-major)
__device__ __align__(16) float g_bias[ND];
__device__ __align__(16) float g_C[(size_t)M_ * GID];     // 25 MB (gi only)

// ------------------------------------------------------------------ PTX helpers
__device__ __forceinline__ uint32_t smem_u32(const void* p) {
    uint32_t a;
    asm("{ .reg .u64 t; cvta.to.shared.u64 t, %1; cvt.u32.u64 %0, t; }" : "=r"(a) : "l"(p));
    return a;
}
__device__ __forceinline__ void cpasync16(uint32_t dst, const void* src) {
    asm volatile("cp.async.cg.shared.global [%0], [%1], 16;" :: "r"(dst), "l"(src) : "memory");
}
#define CP_COMMIT() asm volatile("cp.async.commit_group;" ::: "memory")
#define CP_WAIT(n)  asm volatile("cp.async.wait_group %0;" :: "n"(n) : "memory")

__device__ __forceinline__ void ldsm_x4(uint32_t& r0, uint32_t& r1, uint32_t& r2, uint32_t& r3,
                                        uint32_t addr) {
    asm volatile("ldmatrix.sync.aligned.m8n8.x4.shared.b16 {%0,%1,%2,%3}, [%4];"
                 : "=r"(r0), "=r"(r1), "=r"(r2), "=r"(r3) : "r"(addr));
}
__device__ __forceinline__ void ldsm_x2(uint32_t& r0, uint32_t& r1, uint32_t addr) {
    asm volatile("ldmatrix.sync.aligned.m8n8.x2.shared.b16 {%0,%1}, [%2];"
                 : "=r"(r0), "=r"(r1) : "r"(addr));
}
__device__ __forceinline__ void mma16816(float* d, uint32_t a0, uint32_t a1, uint32_t a2,
                                         uint32_t a3, uint32_t b0, uint32_t b1) {
    asm volatile("mma.sync.aligned.m16n8k16.row.col.f32.f16.f16.f32 "
                 "{%0,%1,%2,%3}, {%4,%5,%6,%7}, {%8,%9}, {%0,%1,%2,%3};"
                 : "+f"(d[0]), "+f"(d[1]), "+f"(d[2]), "+f"(d[3])
                 : "r"(a0), "r"(a1), "r"(a2), "r"(a3), "r"(b0), "r"(b1));
}
__device__ __forceinline__ float tanh_fast(float x) {
    float y;
    asm("tanh.approx.f32 %0, %1;" : "=f"(y) : "f"(x));
    return y;
}
__device__ __forceinline__ float sig_fast(float x) {
    return 0.5f + 0.5f * tanh_fast(0.5f * x);
}
__device__ __forceinline__ uint32_t f2h2(float lo, float hi) {
    uint32_t r;
    asm("cvt.rn.f16x2.f32 %0, %2, %1;" : "=r"(r) : "f"(lo), "f"(hi));
    return r;
}

// ------------------------------------------------------------------ feat: one WARP per (b,t); demo fused in
__device__ __forceinline__ float elu1(float v) { return v > 0.f ? v : __expf(v) - 1.f; }

#define FWARPS 8

struct FeatScratch {
    float x[XDIM];
    float h1[NAG * NHIDD];
    float p[2][NAG][NHIDD];
    float h2a[E_ * NHIDD];
};

__global__ __launch_bounds__(FWARPS * 32) void feat_kernel(
        const float* __restrict__ x,
        const float* __restrict__ ft,
        const float* __restrict__ xd,   const float* __restrict__ Wst,
        const float* __restrict__ bst,
        const float* __restrict__ Wm1a, const float* __restrict__ bm1a,
        const float* __restrict__ Wm1b, const float* __restrict__ bm1b,
        const float* __restrict__ Wm2a, const float* __restrict__ bm2a,
        const float* __restrict__ Wm2b, const float* __restrict__ bm2b,
        const float* __restrict__ Wx2,  const float* __restrict__ bx2) {
    __shared__ FeatScratch sc[FWARPS];
    int w = threadIdx.x >> 5;
    int lane = threadIdx.x & 31;
    int m = blockIdx.x * FWARPS + w;
    int b = m / T_, t = m % T_;
    FeatScratch& s = sc[w];

    const float* xr = x + ((size_t)b * (T_ + 1) + t) * XDIM;
    s.x[lane] = xr[lane];
    if (lane < XDIM - 32) s.x[32 + lane] = xr[32 + lane];
    __syncwarp();

    float h1a_reg[3];
#pragma unroll
    for (int ii = 0; ii < 3; ii++) {
        int i = lane + ii * 32;
        if (i < NAG * NHIDD) {
            int a = i / NHIDD, o = i % NHIDD;
            float acc = bm1a[o];
#pragma unroll
            for (int f = 0; f < NFEAT; f++) acc += s.x[a * NFEAT + f] * Wm1a[o * NFEAT + f];
            h1a_reg[ii] = elu1(acc);
        }
    }
#pragma unroll
    for (int ii = 0; ii < 3; ii++) {
        int i = lane + ii * 32;
        if (i < NAG * NHIDD) s.h1[i] = h1a_reg[ii];
    }
    __syncwarp();
    float h1_reg[3];
#pragma unroll
    for (int ii = 0; ii < 3; ii++) {
        int i = lane + ii * 32;
        if (i < NAG * NHIDD) {
            int a = i / NHIDD, o = i % NHIDD;
            float acc = bm1b[o];
#pragma unroll
            for (int k = 0; k < NHIDD; k++) acc += s.h1[a * NHIDD + k] * Wm1b[o * NHIDD + k];
            h1_reg[ii] = elu1(acc);
        }
    }
    __syncwarp();
#pragma unroll
    for (int ii = 0; ii < 3; ii++) {
        int i = lane + ii * 32;
        if (i < NAG * NHIDD) s.h1[i] = h1_reg[ii];
    }
    __syncwarp();

#pragma unroll
    for (int ii = 0; ii < 5; ii++) {
        int i = lane + ii * 32;
        int part = i / (NAG * NHIDD);
        int rest = i % (NAG * NHIDD);
        int a = rest / NHIDD, o = rest % NHIDD;
        float acc = 0.f;
#pragma unroll
        for (int k = 0; k < NHIDD; k++)
            acc += s.h1[a * NHIDD + k] * Wm2a[o * 16 + part * 8 + k];
        s.p[part][a][o] = acc;
    }
    __syncwarp();

    for (int i = lane; i < E_ * NHIDD; i += 32) {
        int e = i / NHIDD, o = i % NHIDD;
        int r = e / (NAG - 1), jj = e % (NAG - 1);
        int sd = jj < r ? jj : jj + 1;
        s.h2a[i] = elu1(s.p[0][r][o] + s.p[1][sd][o] + bm2a[o]);
    }
    __syncwarp();

    __half* u = g_Uh + (size_t)m * KD;
    for (int i = lane; i < E_ * NHIDD; i += 32) {
        int e = i / NHIDD, o = i % NHIDD;
        float acc = bm2b[o];
#pragma unroll
        for (int k = 0; k < NHIDD; k++) acc += s.h2a[e * NHIDD + k] * Wm2b[o * NHIDD + k];
        u[43 + i] = __float2half(elu1(acc));
    }

    {
        float acc = bx2[lane];
#pragma unroll
        for (int f = 0; f < XDIM - XPERM; f++)
            acc += s.x[XPERM + f] * Wx2[lane * (XDIM - XPERM) + f];
        u[lane] = __float2half(acc);
    }
    if (lane < XSTAT) {
        float acc = bst[lane];
        const float* xdr = xd + (size_t)b * XSTAT;
#pragma unroll
        for (int k = 0; k < XSTAT; k++) acc += xdr[k] * Wst[lane * XSTAT + k];
        u[XEMBD + lane] = __float2half(acc);
    }
    if (lane == 10) u[42] = __float2half(ft[(size_t)b * (T_ + 1) + t]);
    if (lane >= 11 && lane < 16) u[752 + lane] = __float2half(0.f);   // pad 763..767
}

// ------------------------------------------------------------------ repack W -> fp16, n-major; zero out[:,0:2]
__global__ void repack_kernel(const float* __restrict__ Wa1, const float* __restrict__ ba1,
                              const float* __restrict__ Wo1, const float* __restrict__ bo1,
                              const float* __restrict__ Wih, const float* __restrict__ bih,
                              float* __restrict__ out) {
    int idx = blockIdx.x * blockDim.x + threadIdx.x;
    if (idx < ND)
        g_bias[idx] = idx < 128 ? ba1[idx] : (idx < 256 ? bo1[idx - 128] : bih[idx - 256]);

    int stride = gridDim.x * blockDim.x;
    for (int i = idx; i < 2 * M_; i += stride)
        out[(size_t)(i >> 1) * OUTW + (i & 1)] = 0.f;

    for (int i = idx; i < KD * ND; i += stride) {
        int n = i / KD, k = i % KD;
        float v = 0.f;
        if (n < 128) {
            if (k >= 32 && k < 42)       v = Wa1[n * 730 + (k - 32)];
            else if (k >= 43 && k < 763) v = Wa1[n * 730 + 10 + (k - 43)];
        } else if (n < 256) {
            if (k < 763) v = Wo1[(n - 128) * 763 + k];
        } else {
            int r = n - 256;
            if (k < 32)                  v = Wih[r * 753 + k];
            else if (k == 42)            v = Wih[r * 753 + 32];
            else if (k >= 43 && k < 763) v = Wih[r * 753 + 33 + (k - 43)];
        }
        g_Wh[(size_t)n * KD + k] = __float2half(v);
    }
}

// ------------------------------------------------------------------ GEMM helpers (CTA 256x128, 8 warps of 64x64)
#define BK      64
#define NCHUNK  (KD / BK)               // 12
#define ATILEB  (256 * BK * 2)          // 32 KB
#define BTILEB  (128 * BK * 2)          // 16 KB
#define STAGEB  (ATILEB + BTILEB)       // 48 KB
#define NSTAGE  3
#define SMEMB   (NSTAGE * STAGEB)       // 144 KB

__device__ __forceinline__ void load_chunk(uint32_t stage, int m0, int n0,
                                           int koff, int tid) {
    uint32_t sA = stage, sB = stage + ATILEB;
#pragma unroll
    for (int t = 0; t < 8; t++) {
        int i = tid + t * 256;
        int row = i >> 3, cc = i & 7;
        uint32_t off = row * 128 + cc * 16;
        uint32_t sw = off ^ ((off >> 3) & 0x70);
        cpasync16(sA + sw, g_Uh + (size_t)(m0 + row) * KD + koff + cc * 8);
    }
#pragma unroll
    for (int t = 0; t < 4; t++) {
        int i = tid + t * 256;
        int row = i >> 3, cc = i & 7;
        uint32_t off = row * 128 + cc * 16;
        uint32_t sw = off ^ ((off >> 3) & 0x70);
        cpasync16(sB + sw, g_Wh + (size_t)(n0 + row) * KD + koff + cc * 8);
    }
}

// mainloop producing acc[4][8][4] for tile (m0, n0)
__device__ __forceinline__ void gemm_mainloop(uint32_t sb, int m0, int n0, int tid,
                                              float acc[4][8][4]) {
    int wid = tid >> 5, lane = tid & 31;
    int wm = (wid & 3) * 64;
    int wn = (wid >> 2) * 64;
    int arow = (lane & 7) + ((lane >> 3) & 1) * 8;
    int akc  = (lane >> 4) * 8;
    int l2   = lane & 15;
    int brow = l2 & 7;
    int bkc  = ((l2 >> 3) & 1) * 8;

    load_chunk(sb + 0 * STAGEB, m0, n0, 0 * BK, tid);
    CP_COMMIT();
    load_chunk(sb + 1 * STAGEB, m0, n0, 1 * BK, tid);
    CP_COMMIT();

    for (int c = 0; c < NCHUNK; c++) {
        if (c + 1 < NCHUNK) CP_WAIT(1); else CP_WAIT(0);
        __syncthreads();
        if (c + 2 < NCHUNK) {
            load_chunk(sb + ((c + 2) % 3) * STAGEB, m0, n0, (c + 2) * BK, tid);
            CP_COMMIT();
        }
        uint32_t sA = sb + (c % 3) * STAGEB;
        uint32_t sB = sA + ATILEB;
#pragma unroll
        for (int ks = 0; ks < 4; ks++) {
            uint32_t a[4][4];
#pragma unroll
            for (int mt = 0; mt < 4; mt++) {
                uint32_t off = (uint32_t)(wm + mt * 16 + arow) * 128 + (ks * 16 + akc) * 2;
                off ^= (off >> 3) & 0x70;
                ldsm_x4(a[mt][0], a[mt][1], a[mt][2], a[mt][3], sA + off);
            }
#pragma unroll
            for (int nt = 0; nt < 8; nt++) {
                uint32_t off = (uint32_t)(wn + nt * 8 + brow) * 128 + (ks * 16 + bkc) * 2;
                off ^= (off >> 3) & 0x70;
                uint32_t b0, b1;
                ldsm_x2(b0, b1, sB + off);
#pragma unroll
                for (int mt = 0; mt < 4; mt++)
                    mma16816(acc[mt][nt], a[mt][0], a[mt][1], a[mt][2], a[mt][3], b0, b1);
            }
        }
    }
}

// ------------------------------------------------------------------ gemm_gi: gi tiles only (n0 = 256 + bx*128)
__global__ __launch_bounds__(256) void gemm_gi_kernel() {
    extern __shared__ char smem[];
    uint32_t sb = smem_u32(smem);
    int tid = threadIdx.x;
    int wid = tid >> 5, lane = tid & 31;
    int m0 = blockIdx.y * 256;
    int n0 = 256 + blockIdx.x * 128;
    int wm = (wid & 3) * 64;
    int wn = (wid >> 2) * 64;

    float acc[4][8][4];
#pragma unroll
    for (int mt = 0; mt < 4; mt++)
#pragma unroll
        for (int nt = 0; nt < 8; nt++)
#pragma unroll
            for (int r = 0; r < 4; r++) acc[mt][nt][r] = 0.f;

    gemm_mainloop(sb, m0, n0, tid, acc);

    int tq = lane >> 2, tr = lane & 3;
    int cb = n0 - 256;
#pragma unroll
    for (int nt = 0; nt < 8; nt++) {
        int col = wn + nt * 8 + tr * 2;
        float2 bv = *(const float2*)&g_bias[n0 + col];
#pragma unroll
        for (int mt = 0; mt < 4; mt++) {
            size_t row0 = (size_t)m0 + wm + mt * 16 + tq;
            float2 v0 = {acc[mt][nt][0] + bv.x, acc[mt][nt][1] + bv.y};
            float2 v1 = {acc[mt][nt][2] + bv.x, acc[mt][nt][3] + bv.y};
            *(float2*)(g_C + row0 * GID + cb + col) = v0;
            *(float2*)(g_C + (row0 + 8) * GID + cb + col) = v1;
        }
    }
}

// ------------------------------------------------------------------ fused tail: blocks 0..31 GRU, blocks 32..159 head tiles
#define GBATCH 8
#define HP16   136
#define NGRU   32

__global__ __launch_bounds__(256, 1) void tail_kernel(
        const float* __restrict__ Whh, const float* __restrict__ bhh,
        const float* __restrict__ h0,
        const float* __restrict__ Wa2, const float* __restrict__ Wo2,
        float* __restrict__ out) {
    extern __shared__ char smem[];
    int tid = threadIdx.x;
    int wid = tid >> 5, lane = tid & 31;
    int tq = lane >> 2, tr = lane & 3;

    if (blockIdx.x >= NGRU) {
        // ---------------- head-tile GEMM path ----------------
        uint32_t sb = smem_u32(smem);
        int h = blockIdx.x - NGRU;         // 0..127
        int hbx = h & 1;                   // 0 -> a, 1 -> o
        int m0 = (h >> 1) * 256;
        int n0 = hbx * 128;
        int wm = (wid & 3) * 64;
        int wn = (wid >> 2) * 64;

        float acc[4][8][4];
#pragma unroll
        for (int mt = 0; mt < 4; mt++)
#pragma unroll
            for (int nt = 0; nt < 8; nt++)
#pragma unroll
                for (int r = 0; r < 4; r++) acc[mt][nt][r] = 0.f;

        gemm_mainloop(sb, m0, n0, tid, acc);

        const float* w2 = hbx == 0 ? Wa2 : Wo2;
        float part[4][2];
#pragma unroll
        for (int mt = 0; mt < 4; mt++) { part[mt][0] = 0.f; part[mt][1] = 0.f; }
#pragma unroll
        for (int nt = 0; nt < 8; nt++) {
            int col = wn + nt * 8 + tr * 2;
            float2 bv = *(const float2*)&g_bias[n0 + col];
            float w0 = w2[col], w1 = w2[col + 1];
#pragma unroll
            for (int mt = 0; mt < 4; mt++) {
                part[mt][0] += fmaxf(acc[mt][nt][0] + bv.x, 0.f) * w0
                             + fmaxf(acc[mt][nt][1] + bv.y, 0.f) * w1;
                part[mt][1] += fmaxf(acc[mt][nt][2] + bv.x, 0.f) * w0
                             + fmaxf(acc[mt][nt][3] + bv.y, 0.f) * w1;
            }
        }
#pragma unroll
        for (int mt = 0; mt < 4; mt++)
#pragma unroll
            for (int hh = 0; hh < 2; hh++) {
                part[mt][hh] += __shfl_xor_sync(0xFFFFFFFFu, part[mt][hh], 1);
                part[mt][hh] += __shfl_xor_sync(0xFFFFFFFFu, part[mt][hh], 2);
            }
        if (tr == 0) {
#pragma unroll
            for (int mt = 0; mt < 4; mt++) {
                size_t row0 = (size_t)m0 + wm + mt * 16 + tq;
                atomicAdd(out + row0 * OUTW + hbx, part[mt][0]);
                atomicAdd(out + (row0 + 8) * OUTW + hbx, part[mt][1]);
            }
        }
        return;
    }

    // ---------------- GRU path (R11/R14 structure) ----------------
    __shared__ __align__(16) __half s_h16[2][GBATCH][HP16];

    int l2 = lane & 15;
    int brow = l2 & 7;
    int bkc  = ((l2 >> 3) & 1) * 8;
    int b0g = blockIdx.x * GBATCH;
    int j0 = wid * 16 + tq;

    uint32_t sh_base = smem_u32(&s_h16[0][0][0]);

    uint32_t afr[3][8][4];
#pragma unroll
    for (int g = 0; g < 3; g++)
#pragma unroll
        for (int kt = 0; kt < 8; kt++) {
            int row0 = g * HIDD + j0;
            int k0 = kt * 16 + tr * 2;
            const float* w0 = Whh + (size_t)row0 * HIDD + k0;
            const float* w1 = Whh + (size_t)(row0 + 8) * HIDD + k0;
            afr[g][kt][0] = f2h2(w0[0], w0[1]);
            afr[g][kt][1] = f2h2(w1[0], w1[1]);
            afr[g][kt][2] = f2h2(w0[8], w0[9]);
            afr[g][kt][3] = f2h2(w1[8], w1[9]);
        }
    float bb[3][2];
#pragma unroll
    for (int g = 0; g < 3; g++) {
        bb[g][0] = bhh[g * HIDD + j0];
        bb[g][1] = bhh[g * HIDD + j0 + 8];
    }

    float hreg[2][2];
    const float* gibase[2];
    float* outbase[2];
#pragma unroll
    for (int bs = 0; bs < 2; bs++) {
        int b = b0g + 2 * tr + bs;
        hreg[0][bs] = h0[(size_t)b * HIDD + j0];
        hreg[1][bs] = h0[(size_t)b * HIDD + j0 + 8];
        gibase[bs] = g_C + ((size_t)b * T_) * GID + j0;
        outbase[bs] = out + ((size_t)b * T_) * OUTW + 2 + j0;
    }
    for (int i = tid; i < GBATCH * HIDD; i += 256)
        s_h16[0][i >> 7][i & 127] =
            __float2half(h0[(size_t)(b0g + (i >> 7)) * HIDD + (i & 127)]);

    float gic[3][4], gin[3][4];
#pragma unroll
    for (int g = 0; g < 3; g++)
#pragma unroll
        for (int js = 0; js < 2; js++)
#pragma unroll
            for (int bs = 0; bs < 2; bs++)
                gic[g][js * 2 + bs] = gibase[bs][g * HIDD + js * 8];
    __syncthreads();

    for (int t = 0; t < T_; t++) {
        if (t + 1 < T_) {
#pragma unroll
            for (int g = 0; g < 3; g++)
#pragma unroll
                for (int js = 0; js < 2; js++)
#pragma unroll
                    for (int bs = 0; bs < 2; bs++)
                        gin[g][js * 2 + bs] =
                            gibase[bs][(size_t)(t + 1) * GID + g * HIDD + js * 8];
        }

        int p = t & 1;
        uint32_t hb = sh_base + (uint32_t)p * (GBATCH * HP16 * 2)
                    + (uint32_t)brow * (HP16 * 2) + (uint32_t)bkc * 2;

        float d[3][4], e[3][4];
#pragma unroll
        for (int js = 0; js < 2; js++)
#pragma unroll
            for (int bs = 0; bs < 2; bs++) {
                int q = js * 2 + bs;
                d[0][q] = gic[0][q] + bb[0][js];
                d[1][q] = gic[1][q] + bb[1][js];
                d[2][q] = bb[2][js];
                e[0][q] = 0.f; e[1][q] = 0.f; e[2][q] = 0.f;
            }

#pragma unroll
        for (int kt = 0; kt < 8; kt++) {
            uint32_t bf0, bf1;
            ldsm_x2(bf0, bf1, hb + (uint32_t)kt * 32);
            float* dst0 = (kt < 4) ? d[0] : e[0];
            float* dst1 = (kt < 4) ? d[1] : e[1];
            float* dst2 = (kt < 4) ? d[2] : e[2];
            mma16816(dst0, afr[0][kt][0], afr[0][kt][1], afr[0][kt][2], afr[0][kt][3], bf0, bf1);
            mma16816(dst1, afr[1][kt][0], afr[1][kt][1], afr[1][kt][2], afr[1][kt][3], bf0, bf1);
            mma16816(dst2, afr[2][kt][0], afr[2][kt][1], afr[2][kt][2], afr[2][kt][3], bf0, bf1);
        }

#pragma unroll
        for (int js = 0; js < 2; js++)
#pragma unroll
            for (int bs = 0; bs < 2; bs++) {
                int q = js * 2 + bs;
                float r = sig_fast(d[0][q] + e[0][q]);
                float z = sig_fast(d[1][q] + e[1][q]);
                float n = tanh_fast(gic[2][q] + r * (d[2][q] + e[2][q]));
                float hv = (1.f - z) * n + z * hreg[js][bs];
                hreg[js][bs] = hv;
                s_h16[p ^ 1][2 * tr + bs][j0 + js * 8] = __float2half(hv);
                outbase[bs][(size_t)t * OUTW + js * 8] = hv;
            }

#pragma unroll
        for (int g = 0; g < 3; g++)
#pragma unroll
            for (int q = 0; q < 4; q++) gic[g][q] = gin[g][q];
        __syncthreads();
    }
}

// ------------------------------------------------------------------
extern "C" void kernel_launch(void* const* d_in, const int* in_sizes, int n_in,
                              void* d_out, int out_size) {
    const float* x     = (const float*)d_in[0];
    const float* xdemo = (const float*)d_in[1];
    const float* ft    = (const float*)d_in[2];
    const float* h0    = (const float*)d_in[3];
    const float* Wx2   = (const float*)d_in[4];
    const float* bx2   = (const float*)d_in[5];
    const float* Wst   = (const float*)d_in[6];
    const float* bst   = (const float*)d_in[7];
    const float* Wm1a  = (const float*)d_in[8];
    const float* bm1a  = (const float*)d_in[9];
    const float* Wm1b  = (const float*)d_in[10];
    const float* bm1b  = (const float*)d_in[11];
    const float* Wm2a  = (const float*)d_in[12];
    const float* bm2a  = (const float*)d_in[13];
    const float* Wm2b  = (const float*)d_in[14];
    const float* bm2b  = (const float*)d_in[15];
    const float* Wa1   = (const float*)d_in[16];
    const float* ba1   = (const float*)d_in[17];
    const float* Wa2   = (const float*)d_in[18];
    const float* Wo1   = (const float*)d_in[19];
    const float* bo1   = (const float*)d_in[20];
    const float* Wo2   = (const float*)d_in[21];
    const float* Wih   = (const float*)d_in[22];
    const float* bih   = (const float*)d_in[23];
    const float* Whh   = (const float*)d_in[24];
    const float* bhh   = (const float*)d_in[25];
    float* out = (float*)d_out;

    cudaFuncSetAttribute(gemm_gi_kernel,
                         cudaFuncAttributeMaxDynamicSharedMemorySize, SMEMB);
    cudaFuncSetAttribute(tail_kernel,
                         cudaFuncAttributeMaxDynamicSharedMemorySize, SMEMB);

    repack_kernel<<<480, 256>>>(Wa1, ba1, Wo1, bo1, Wih, bih, out);
    feat_kernel<<<M_ / FWARPS, FWARPS * 32>>>(x, ft, xdemo, Wst, bst,
                                              Wm1a, bm1a, Wm1b, bm1b,
                                              Wm2a, bm2a, Wm2b, bm2b, Wx2, bx2);
    gemm_gi_kernel<<<dim3(3, M_ / 256), 256, SMEMB>>>();
    tail_kernel<<<NGRU + 128, 256, SMEMB>>>(Whh, bhh, h0, Wa2, Wo2, out);
}

// round 16
// speedup vs baseline: 1.4513x; 1.0937x over previous
#include <cuda_runtime.h>
#include <cuda_fp16.h>
#include <math.h>
#include <stdint.h>

#define B_    256
#define T_    64
#define NAG   10
#define NFEAT 4
#define XDIM  44
#define XPERM 40
#define XSTAT 10
#define HIDD  128
#define XEMBD 32
#define NHIDD 8
#define E_    90
#define M_    (B_ * T_)      // 16384
#define KD    768            // padded from 763
#define ND    640            // logical: 128 (a) + 128 (o) + 384 (gi)
#define GID   384            // stored C width (gi only)
#define OUTW  130

// ---- scratch ----
__device__ __align__(16) __half g_Uh[(size_t)M_ * KD];    // 24 MB
__device__ __align__(16) __half g_Wh[(size_t)ND * KD];    // 0.94 MB (n-major)
__device__ __align__(16) float g_bias[ND];
__device__ __align__(16) float g_C[(size_t)M_ * GID];     // 25 MB (gi only)
__device__ int g_gi_flag[32];                             // per-GRU-group gi completion

// ------------------------------------------------------------------ PTX helpers
__device__ __forceinline__ uint32_t smem_u32(const void* p) {
    uint32_t a;
    asm("{ .reg .u64 t; cvta.to.shared.u64 t, %1; cvt.u32.u64 %0, t; }" : "=r"(a) : "l"(p));
    return a;
}
__device__ __forceinline__ void cpasync16(uint32_t dst, const void* src) {
    asm volatile("cp.async.cg.shared.global [%0], [%1], 16;" :: "r"(dst), "l"(src) : "memory");
}
#define CP_COMMIT() asm volatile("cp.async.commit_group;" ::: "memory")
#define CP_WAIT(n)  asm volatile("cp.async.wait_group %0;" :: "n"(n) : "memory")

__device__ __forceinline__ void ldsm_x4(uint32_t& r0, uint32_t& r1, uint32_t& r2, uint32_t& r3,
                                        uint32_t addr) {
    asm volatile("ldmatrix.sync.aligned.m8n8.x4.shared.b16 {%0,%1,%2,%3}, [%4];"
                 : "=r"(r0), "=r"(r1), "=r"(r2), "=r"(r3) : "r"(addr));
}
__device__ __forceinline__ void ldsm_x2(uint32_t& r0, uint32_t& r1, uint32_t addr) {
    asm volatile("ldmatrix.sync.aligned.m8n8.x2.shared.b16 {%0,%1}, [%2];"
                 : "=r"(r0), "=r"(r1) : "r"(addr));
}
__device__ __forceinline__ void mma16816(float* d, uint32_t a0, uint32_t a1, uint32_t a2,
                                         uint32_t a3, uint32_t b0, uint32_t b1) {
    asm volatile("mma.sync.aligned.m16n8k16.row.col.f32.f16.f16.f32 "
                 "{%0,%1,%2,%3}, {%4,%5,%6,%7}, {%8,%9}, {%0,%1,%2,%3};"
                 : "+f"(d[0]), "+f"(d[1]), "+f"(d[2]), "+f"(d[3])
                 : "r"(a0), "r"(a1), "r"(a2), "r"(a3), "r"(b0), "r"(b1));
}
__device__ __forceinline__ float tanh_fast(float x) {
    float y;
    asm("tanh.approx.f32 %0, %1;" : "=f"(y) : "f"(x));
    return y;
}
__device__ __forceinline__ float sig_fast(float x) {
    return 0.5f + 0.5f * tanh_fast(0.5f * x);
}
__device__ __forceinline__ uint32_t f2h2(float lo, float hi) {
    uint32_t r;
    asm("cvt.rn.f16x2.f32 %0, %2, %1;" : "=r"(r) : "f"(lo), "f"(hi));
    return r;
}

// ------------------------------------------------------------------ feat body (one warp per (b,t))
__device__ __forceinline__ float elu1(float v) { return v > 0.f ? v : __expf(v) - 1.f; }

#define FWARPS 8
#define NFEATBLK (M_ / FWARPS)    // 2048
#define NREPBLK  480

struct FeatScratch {
    float x[XDIM];
    float h1[NAG * NHIDD];
    float p[2][NAG][NHIDD];
    float h2a[E_ * NHIDD];
};

__device__ void feat_body(
        int fb,
        const float* __restrict__ x,
        const float* __restrict__ ft,
        const float* __restrict__ xd,   const float* __restrict__ Wst,
        const float* __restrict__ bst,
        const float* __restrict__ Wm1a, const float* __restrict__ bm1a,
        const float* __restrict__ Wm1b, const float* __restrict__ bm1b,
        const float* __restrict__ Wm2a, const float* __restrict__ bm2a,
        const float* __restrict__ Wm2b, const float* __restrict__ bm2b,
        const float* __restrict__ Wx2,  const float* __restrict__ bx2,
        FeatScratch* sc) {
    int w = threadIdx.x >> 5;
    int lane = threadIdx.x & 31;
    int m = fb * FWARPS + w;
    int b = m / T_, t = m % T_;
    FeatScratch& s = sc[w];

    const float* xr = x + ((size_t)b * (T_ + 1) + t) * XDIM;
    s.x[lane] = xr[lane];
    if (lane < XDIM - 32) s.x[32 + lane] = xr[32 + lane];
    __syncwarp();

    float h1a_reg[3];
#pragma unroll
    for (int ii = 0; ii < 3; ii++) {
        int i = lane + ii * 32;
        if (i < NAG * NHIDD) {
            int a = i / NHIDD, o = i % NHIDD;
            float acc = bm1a[o];
#pragma unroll
            for (int f = 0; f < NFEAT; f++) acc += s.x[a * NFEAT + f] * Wm1a[o * NFEAT + f];
            h1a_reg[ii] = elu1(acc);
        }
    }
#pragma unroll
    for (int ii = 0; ii < 3; ii++) {
        int i = lane + ii * 32;
        if (i < NAG * NHIDD) s.h1[i] = h1a_reg[ii];
    }
    __syncwarp();
    float h1_reg[3];
#pragma unroll
    for (int ii = 0; ii < 3; ii++) {
        int i = lane + ii * 32;
        if (i < NAG * NHIDD) {
            int a = i / NHIDD, o = i % NHIDD;
            float acc = bm1b[o];
#pragma unroll
            for (int k = 0; k < NHIDD; k++) acc += s.h1[a * NHIDD + k] * Wm1b[o * NHIDD + k];
            h1_reg[ii] = elu1(acc);
        }
    }
    __syncwarp();
#pragma unroll
    for (int ii = 0; ii < 3; ii++) {
        int i = lane + ii * 32;
        if (i < NAG * NHIDD) s.h1[i] = h1_reg[ii];
    }
    __syncwarp();

#pragma unroll
    for (int ii = 0; ii < 5; ii++) {
        int i = lane + ii * 32;
        int part = i / (NAG * NHIDD);
        int rest = i % (NAG * NHIDD);
        int a = rest / NHIDD, o = rest % NHIDD;
        float acc = 0.f;
#pragma unroll
        for (int k = 0; k < NHIDD; k++)
            acc += s.h1[a * NHIDD + k] * Wm2a[o * 16 + part * 8 + k];
        s.p[part][a][o] = acc;
    }
    __syncwarp();

    for (int i = lane; i < E_ * NHIDD; i += 32) {
        int e = i / NHIDD, o = i % NHIDD;
        int r = e / (NAG - 1), jj = e % (NAG - 1);
        int sd = jj < r ? jj : jj + 1;
        s.h2a[i] = elu1(s.p[0][r][o] + s.p[1][sd][o] + bm2a[o]);
    }
    __syncwarp();

    __half* u = g_Uh + (size_t)m * KD;
    for (int i = lane; i < E_ * NHIDD; i += 32) {
        int e = i / NHIDD, o = i % NHIDD;
        float acc = bm2b[o];
#pragma unroll
        for (int k = 0; k < NHIDD; k++) acc += s.h2a[e * NHIDD + k] * Wm2b[o * NHIDD + k];
        u[43 + i] = __float2half(elu1(acc));
    }

    {
        float acc = bx2[lane];
#pragma unroll
        for (int f = 0; f < XDIM - XPERM; f++)
            acc += s.x[XPERM + f] * Wx2[lane * (XDIM - XPERM) + f];
        u[lane] = __float2half(acc);
    }
    if (lane < XSTAT) {
        float acc = bst[lane];
        const float* xdr = xd + (size_t)b * XSTAT;
#pragma unroll
        for (int k = 0; k < XSTAT; k++) acc += xdr[k] * Wst[lane * XSTAT + k];
        u[XEMBD + lane] = __float2half(acc);
    }
    if (lane == 10) u[42] = __float2half(ft[(size_t)b * (T_ + 1) + t]);
    if (lane >= 11 && lane < 16) u[752 + lane] = __float2half(0.f);   // pad 763..767
}

// ------------------------------------------------------------------ launch A: feat blocks + repack blocks (concurrent)
__global__ __launch_bounds__(256) void prep_kernel(
        const float* __restrict__ x,    const float* __restrict__ ft,
        const float* __restrict__ xd,   const float* __restrict__ Wst,
        const float* __restrict__ bst,
        const float* __restrict__ Wm1a, const float* __restrict__ bm1a,
        const float* __restrict__ Wm1b, const float* __restrict__ bm1b,
        const float* __restrict__ Wm2a, const float* __restrict__ bm2a,
        const float* __restrict__ Wm2b, const float* __restrict__ bm2b,
        const float* __restrict__ Wx2,  const float* __restrict__ bx2,
        const float* __restrict__ Wa1,  const float* __restrict__ ba1,
        const float* __restrict__ Wo1,  const float* __restrict__ bo1,
        const float* __restrict__ Wih,  const float* __restrict__ bih,
        float* __restrict__ out) {
    __shared__ FeatScratch sc[FWARPS];
    if (blockIdx.x < NFEATBLK) {
        feat_body(blockIdx.x, x, ft, xd, Wst, bst, Wm1a, bm1a, Wm1b, bm1b,
                  Wm2a, bm2a, Wm2b, bm2b, Wx2, bx2, sc);
        return;
    }
    // ---- repack path ----
    int rb = blockIdx.x - NFEATBLK;      // 0..479
    int idx = rb * blockDim.x + threadIdx.x;
    if (idx < ND)
        g_bias[idx] = idx < 128 ? ba1[idx] : (idx < 256 ? bo1[idx - 128] : bih[idx - 256]);
    if (idx < 32) g_gi_flag[idx] = 0;

    int stride = NREPBLK * blockDim.x;
    for (int i = idx; i < 2 * M_; i += stride)
        out[(size_t)(i >> 1) * OUTW + (i & 1)] = 0.f;

    for (int i = idx; i < KD * ND; i += stride) {
        int n = i / KD, k = i % KD;
        float v = 0.f;
        if (n < 128) {
            if (k >= 32 && k < 42)       v = Wa1[n * 730 + (k - 32)];
            else if (k >= 43 && k < 763) v = Wa1[n * 730 + 10 + (k - 43)];
        } else if (n < 256) {
            if (k < 763) v = Wo1[(n - 128) * 763 + k];
        } else {
            int r = n - 256;
            if (k < 32)                  v = Wih[r * 753 + k];
            else if (k == 42)            v = Wih[r * 753 + 32];
            else if (k >= 43 && k < 763) v = Wih[r * 753 + 33 + (k - 43)];
        }
        g_Wh[(size_t)n * KD + k] = __float2half(v);
    }
}

// ------------------------------------------------------------------ GEMM helpers (CTA 256x128, 8 warps of 64x64)
#define BK      64
#define NCHUNK  (KD / BK)               // 12
#define ATILEB  (256 * BK * 2)          // 32 KB
#define BTILEB  (128 * BK * 2)          // 16 KB
#define STAGEB  (ATILEB + BTILEB)       // 48 KB
#define NSTAGE  3
#define SMEMB   (NSTAGE * STAGEB)       // 144 KB

__device__ __forceinline__ void load_chunk(uint32_t stage, int m0, int n0,
                                           int koff, int tid) {
    uint32_t sA = stage, sB = stage + ATILEB;
#pragma unroll
    for (int t = 0; t < 8; t++) {
        int i = tid + t * 256;
        int row = i >> 3, cc = i & 7;
        uint32_t off = row * 128 + cc * 16;
        uint32_t sw = off ^ ((off >> 3) & 0x70);
        cpasync16(sA + sw, g_Uh + (size_t)(m0 + row) * KD + koff + cc * 8);
    }
#pragma unroll
    for (int t = 0; t < 4; t++) {
        int i = tid + t * 256;
        int row = i >> 3, cc = i & 7;
        uint32_t off = row * 128 + cc * 16;
        uint32_t sw = off ^ ((off >> 3) & 0x70);
        cpasync16(sB + sw, g_Wh + (size_t)(n0 + row) * KD + koff + cc * 8);
    }
}

__device__ __forceinline__ void gemm_mainloop(uint32_t sb, int m0, int n0, int tid,
                                              float acc[4][8][4]) {
    int wid = tid >> 5, lane = tid & 31;
    int wm = (wid & 3) * 64;
    int wn = (wid >> 2) * 64;
    int arow = (lane & 7) + ((lane >> 3) & 1) * 8;
    int akc  = (lane >> 4) * 8;
    int l2   = lane & 15;
    int brow = l2 & 7;
    int bkc  = ((l2 >> 3) & 1) * 8;

    load_chunk(sb + 0 * STAGEB, m0, n0, 0 * BK, tid);
    CP_COMMIT();
    load_chunk(sb + 1 * STAGEB, m0, n0, 1 * BK, tid);
    CP_COMMIT();

    for (int c = 0; c < NCHUNK; c++) {
        if (c + 1 < NCHUNK) CP_WAIT(1); else CP_WAIT(0);
        __syncthreads();
        if (c + 2 < NCHUNK) {
            load_chunk(sb + ((c + 2) % 3) * STAGEB, m0, n0, (c + 2) * BK, tid);
            CP_COMMIT();
        }
        uint32_t sA = sb + (c % 3) * STAGEB;
        uint32_t sB = sA + ATILEB;
#pragma unroll
        for (int ks = 0; ks < 4; ks++) {
            uint32_t a[4][4];
#pragma unroll
            for (int mt = 0; mt < 4; mt++) {
                uint32_t off = (uint32_t)(wm + mt * 16 + arow) * 128 + (ks * 16 + akc) * 2;
                off ^= (off >> 3) & 0x70;
                ldsm_x4(a[mt][0], a[mt][1], a[mt][2], a[mt][3], sA + off);
            }
#pragma unroll
            for (int nt = 0; nt < 8; nt++) {
                uint32_t off = (uint32_t)(wn + nt * 8 + brow) * 128 + (ks * 16 + bkc) * 2;
                off ^= (off >> 3) & 0x70;
                uint32_t b0, b1;
                ldsm_x2(b0, b1, sB + off);
#pragma unroll
                for (int mt = 0; mt < 4; mt++)
                    mma16816(acc[mt][nt], a[mt][0], a[mt][1], a[mt][2], a[mt][3], b0, b1);
            }
        }
    }
}

// ------------------------------------------------------------------ launch B: mega kernel
// blocks [0,192): gi tiles (mtile = bx/3, col = bx%3) -> flag group bx/6
// blocks [192,224): GRU group g = bx-192 (spins on g_gi_flag[g] == 6)
// blocks [224,352): head tiles
#define NGI    192
#define NGRUB  32
#define GBATCH 8
#define HP16   136

__global__ __launch_bounds__(256, 1) void mega_kernel(
        const float* __restrict__ Whh, const float* __restrict__ bhh,
        const float* __restrict__ h0,
        const float* __restrict__ Wa2, const float* __restrict__ Wo2,
        float* __restrict__ out) {
    extern __shared__ char smem[];
    int tid = threadIdx.x;
    int wid = tid >> 5, lane = tid & 31;
    int tq = lane >> 2, tr = lane & 3;

    if (blockIdx.x < NGI) {
        // ---------------- gi tile ----------------
        uint32_t sb = smem_u32(smem);
        int mtile = blockIdx.x / 3, col = blockIdx.x % 3;
        int m0 = mtile * 256;
        int n0 = 256 + col * 128;
        int wm = (wid & 3) * 64;
        int wn = (wid >> 2) * 64;

        float acc[4][8][4];
#pragma unroll
        for (int mt = 0; mt < 4; mt++)
#pragma unroll
            for (int nt = 0; nt < 8; nt++)
#pragma unroll
                for (int r = 0; r < 4; r++) acc[mt][nt][r] = 0.f;

        gemm_mainloop(sb, m0, n0, tid, acc);

        int cb = n0 - 256;
#pragma unroll
        for (int nt = 0; nt < 8; nt++) {
            int colj = wn + nt * 8 + tr * 2;
            float2 bv = *(const float2*)&g_bias[n0 + colj];
#pragma unroll
            for (int mt = 0; mt < 4; mt++) {
                size_t row0 = (size_t)m0 + wm + mt * 16 + tq;
                float2 v0 = {acc[mt][nt][0] + bv.x, acc[mt][nt][1] + bv.y};
                float2 v1 = {acc[mt][nt][2] + bv.x, acc[mt][nt][3] + bv.y};
                *(float2*)(g_C + row0 * GID + cb + colj) = v0;
                *(float2*)(g_C + (row0 + 8) * GID + cb + colj) = v1;
            }
        }
        // publish completion
        __threadfence();
        __syncthreads();
        if (tid == 0) atomicAdd(&g_gi_flag[blockIdx.x / 6], 1);
        return;
    }

    if (blockIdx.x >= NGI + NGRUB) {
        // ---------------- head tile ----------------
        uint32_t sb = smem_u32(smem);
        int h = blockIdx.x - (NGI + NGRUB);   // 0..127
        int hbx = h & 1;
        int m0 = (h >> 1) * 256;
        int n0 = hbx * 128;
        int wm = (wid & 3) * 64;
        int wn = (wid >> 2) * 64;

        float acc[4][8][4];
#pragma unroll
        for (int mt = 0; mt < 4; mt++)
#pragma unroll
            for (int nt = 0; nt < 8; nt++)
#pragma unroll
                for (int r = 0; r < 4; r++) acc[mt][nt][r] = 0.f;

        gemm_mainloop(sb, m0, n0, tid, acc);

        const float* w2 = hbx == 0 ? Wa2 : Wo2;
        float part[4][2];
#pragma unroll
        for (int mt = 0; mt < 4; mt++) { part[mt][0] = 0.f; part[mt][1] = 0.f; }
#pragma unroll
        for (int nt = 0; nt < 8; nt++) {
            int colj = wn + nt * 8 + tr * 2;
            float2 bv = *(const float2*)&g_bias[n0 + colj];
            float w0 = w2[colj], w1 = w2[colj + 1];
#pragma unroll
            for (int mt = 0; mt < 4; mt++) {
                part[mt][0] += fmaxf(acc[mt][nt][0] + bv.x, 0.f) * w0
                             + fmaxf(acc[mt][nt][1] + bv.y, 0.f) * w1;
                part[mt][1] += fmaxf(acc[mt][nt][2] + bv.x, 0.f) * w0
                             + fmaxf(acc[mt][nt][3] + bv.y, 0.f) * w1;
            }
        }
#pragma unroll
        for (int mt = 0; mt < 4; mt++)
#pragma unroll
            for (int hh = 0; hh < 2; hh++) {
                part[mt][hh] += __shfl_xor_sync(0xFFFFFFFFu, part[mt][hh], 1);
                part[mt][hh] += __shfl_xor_sync(0xFFFFFFFFu, part[mt][hh], 2);
            }
        if (tr == 0) {
#pragma unroll
            for (int mt = 0; mt < 4; mt++) {
                size_t row0 = (size_t)m0 + (wid & 3) * 64 + mt * 16 + tq;
                atomicAdd(out + row0 * OUTW + hbx, part[mt][0]);
                atomicAdd(out + (row0 + 8) * OUTW + hbx, part[mt][1]);
            }
        }
        return;
    }

    // ---------------- GRU path ----------------
    __shared__ __align__(16) __half s_h16[2][GBATCH][HP16];

    int g_blk = blockIdx.x - NGI;        // 0..31
    int l2 = lane & 15;
    int brow = l2 & 7;
    int bkc  = ((l2 >> 3) & 1) * 8;
    int b0g = g_blk * GBATCH;
    int j0 = wid * 16 + tq;

    uint32_t sh_base = smem_u32(&s_h16[0][0][0]);

    uint32_t afr[3][8][4];
#pragma unroll
    for (int g = 0; g < 3; g++)
#pragma unroll
        for (int kt = 0; kt < 8; kt++) {
            int row0 = g * HIDD + j0;
            int k0 = kt * 16 + tr * 2;
            const float* w0 = Whh + (size_t)row0 * HIDD + k0;
            const float* w1 = Whh + (size_t)(row0 + 8) * HIDD + k0;
            afr[g][kt][0] = f2h2(w0[0], w0[1]);
            afr[g][kt][1] = f2h2(w1[0], w1[1]);
            afr[g][kt][2] = f2h2(w0[8], w0[9]);
            afr[g][kt][3] = f2h2(w1[8], w1[9]);
        }
    float bb[3][2];
#pragma unroll
    for (int g = 0; g < 3; g++) {
        bb[g][0] = bhh[g * HIDD + j0];
        bb[g][1] = bhh[g * HIDD + j0 + 8];
    }

    float hreg[2][2];
    const float* gibase[2];
    float* outbase[2];
#pragma unroll
    for (int bs = 0; bs < 2; bs++) {
        int b = b0g + 2 * tr + bs;
        hreg[0][bs] = h0[(size_t)b * HIDD + j0];
        hreg[1][bs] = h0[(size_t)b * HIDD + j0 + 8];
        gibase[bs] = g_C + ((size_t)b * T_) * GID + j0;
        outbase[bs] = out + ((size_t)b * T_) * OUTW + 2 + j0;
    }
    for (int i = tid; i < GBATCH * HIDD; i += 256)
        s_h16[0][i >> 7][i & 127] =
            __float2half(h0[(size_t)(b0g + (i >> 7)) * HIDD + (i & 127)]);

    // wait for this group's 6 gi tiles
    if (tid == 0) {
        const int* fp = &g_gi_flag[g_blk];
        int v;
        do {
            asm volatile("ld.global.acquire.gpu.b32 %0, [%1];" : "=r"(v) : "l"(fp));
        } while (v < 6);
    }
    __syncthreads();
    __threadfence();

    float gic[3][4], gin[3][4];
#pragma unroll
    for (int g = 0; g < 3; g++)
#pragma unroll
        for (int js = 0; js < 2; js++)
#pragma unroll
            for (int bs = 0; bs < 2; bs++)
                gic[g][js * 2 + bs] = gibase[bs][g * HIDD + js * 8];
    __syncthreads();

    for (int t = 0; t < T_; t++) {
        if (t + 1 < T_) {
#pragma unroll
            for (int g = 0; g < 3; g++)
#pragma unroll
                for (int js = 0; js < 2; js++)
#pragma unroll
                    for (int bs = 0; bs < 2; bs++)
                        gin[g][js * 2 + bs] =
                            gibase[bs][(size_t)(t + 1) * GID + g * HIDD + js * 8];
        }

        int p = t & 1;
        uint32_t hb = sh_base + (uint32_t)p * (GBATCH * HP16 * 2)
                    + (uint32_t)brow * (HP16 * 2) + (uint32_t)bkc * 2;

        float d[3][4], e[3][4];
#pragma unroll
        for (int js = 0; js < 2; js++)
#pragma unroll
            for (int bs = 0; bs < 2; bs++) {
                int q = js * 2 + bs;
                d[0][q] = gic[0][q] + bb[0][js];
                d[1][q] = gic[1][q] + bb[1][js];
                d[2][q] = bb[2][js];
                e[0][q] = 0.f; e[1][q] = 0.f; e[2][q] = 0.f;
            }

#pragma unroll
        for (int kt = 0; kt < 8; kt++) {
            uint32_t bf0, bf1;
            ldsm_x2(bf0, bf1, hb + (uint32_t)kt * 32);
            float* dst0 = (kt < 4) ? d[0] : e[0];
            float* dst1 = (kt < 4) ? d[1] : e[1];
            float* dst2 = (kt < 4) ? d[2] : e[2];
            mma16816(dst0, afr[0][kt][0], afr[0][kt][1], afr[0][kt][2], afr[0][kt][3], bf0, bf1);
            mma16816(dst1, afr[1][kt][0], afr[1][kt][1], afr[1][kt][2], afr[1][kt][3], bf0, bf1);
            mma16816(dst2, afr[2][kt][0], afr[2][kt][1], afr[2][kt][2], afr[2][kt][3], bf0, bf1);
        }

#pragma unroll
        for (int js = 0; js < 2; js++)
#pragma unroll
            for (int bs = 0; bs < 2; bs++) {
                int q = js * 2 + bs;
                float r = sig_fast(d[0][q] + e[0][q]);
                float z = sig_fast(d[1][q] + e[1][q]);
                float n = tanh_fast(gic[2][q] + r * (d[2][q] + e[2][q]));
                float hv = (1.f - z) * n + z * hreg[js][bs];
                hreg[js][bs] = hv;
                s_h16[p ^ 1][2 * tr + bs][j0 + js * 8] = __float2half(hv);
                outbase[bs][(size_t)t * OUTW + js * 8] = hv;
            }

#pragma unroll
        for (int g = 0; g < 3; g++)
#pragma unroll
            for (int q = 0; q < 4; q++) gic[g][q] = gin[g][q];
        __syncthreads();
    }
}

// ------------------------------------------------------------------
extern "C" void kernel_launch(void* const* d_in, const int* in_sizes, int n_in,
                              void* d_out, int out_size) {
    const float* x     = (const float*)d_in[0];
    const float* xdemo = (const float*)d_in[1];
    const float* ft    = (const float*)d_in[2];
    const float* h0    = (const float*)d_in[3];
    const float* Wx2   = (const float*)d_in[4];
    const float* bx2   = (const float*)d_in[5];
    const float* Wst   = (const float*)d_in[6];
    const float* bst   = (const float*)d_in[7];
    const float* Wm1a  = (const float*)d_in[8];
    const float* bm1a  = (const float*)d_in[9];
    const float* Wm1b  = (const float*)d_in[10];
    const float* bm1b  = (const float*)d_in[11];
    const float* Wm2a  = (const float*)d_in[12];
    const float* bm2a  = (const float*)d_in[13];
    const float* Wm2b  = (const float*)d_in[14];
    const float* bm2b  = (const float*)d_in[15];
    const float* Wa1   = (const float*)d_in[16];
    const float* ba1   = (const float*)d_in[17];
    const float* Wa2   = (const float*)d_in[18];
    const float* Wo1   = (const float*)d_in[19];
    const float* bo1   = (const float*)d_in[20];
    const float* Wo2   = (const float*)d_in[21];
    const float* Wih   = (const float*)d_in[22];
    const float* bih   = (const float*)d_in[23];
    const float* Whh   = (const float*)d_in[24];
    const float* bhh   = (const float*)d_in[25];
    float* out = (float*)d_out;

    cudaFuncSetAttribute(mega_kernel,
                         cudaFuncAttributeMaxDynamicSharedMemorySize, SMEMB);

    prep_kernel<<<NFEATBLK + NREPBLK, 256>>>(
        x, ft, xdemo, Wst, bst, Wm1a, bm1a, Wm1b, bm1b,
        Wm2a, bm2a, Wm2b, bm2b, Wx2, bx2,
        Wa1, ba1, Wo1, bo1, Wih, bih, out);
    mega_kernel<<<NGI + NGRUB + 128, 256, SMEMB>>>(Whh, bhh, h0, Wa2, Wo2, out);
}